// round 15
// baseline (speedup 1.0000x reference)
#include <cuda_runtime.h>
#include <cuda_bf16.h>
#include <math.h>
#include <stdint.h>

// ---------------- problem constants ----------------
#define BB   4
#define NN_  512
#define DD   512
#define HH   8
#define DK   64
#define BH   32            // BB*HH
#define NM   (512*512)     // per-(b,h) matrix elems
#define EPSF 1e-6f

// ---------------- scratch (device globals; no runtime alloc) ----------------
__device__ float g_q0[BH*NN_*DK];
__device__ float g_k0[BH*NN_*DK];
__device__ float g_v0[BH*NN_*DK];
__device__ float g_q1[BH*NN_*DK];
__device__ float g_k1[BH*NN_*DK];
__device__ float g_v1[BH*NN_*DK];
__device__ float g_vT[BH*DK*NN_];    // vT[bh][d][n], d = 0..63

__device__ float g_S0 [BH*NM];       // fp32 (softmax input)
__device__ float g_S1 [BH*NM];
__device__ float g_A0 [BH*NM];       // fp32 (gate leading term)
__device__ float g_M  [BH*NM];

// bf16 gate-feature copies + GEMM operands
__device__ __nv_bfloat16 g_S0b [BH*NM];
__device__ __nv_bfloat16 g_S1b [BH*NM];
__device__ __nv_bfloat16 g_S0Tb[BH*NM];
__device__ __nv_bfloat16 g_S1Tb[BH*NM];
__device__ __nv_bfloat16 g_Cfb [BH*NM];
__device__ __nv_bfloat16 g_Cbb [BH*NM];
__device__ __nv_bfloat16 g_A0b [BH*NM];
__device__ __nv_bfloat16 g_A1b [BH*NM];
__device__ __nv_bfloat16 g_A0Tb[BH*NM];
__device__ __nv_bfloat16 g_A1Tb[BH*NM];

__device__ float g_rowsum[BH*NN_];
__device__ float g_attn[BB*NN_*DD];

// ================= small PTX helpers =================
__device__ __forceinline__ uint32_t smem_u32(const void* p) {
    uint32_t a;
    asm("{ .reg .u64 t; cvta.to.shared.u64 t, %1; cvt.u32.u64 %0, t; }" : "=r"(a) : "l"(p));
    return a;
}
__device__ __forceinline__ uint32_t swz128(uint32_t off) { return off ^ ((off >> 3) & 0x70); }

__device__ __forceinline__ void cpasync16(uint32_t dst, const void* src) {
    asm volatile("cp.async.cg.shared.global [%0], [%1], 16;" :: "r"(dst), "l"(src));
}
__device__ __forceinline__ void cp_commit() { asm volatile("cp.async.commit_group;" ::: "memory"); }
template<int N> __device__ __forceinline__ void cp_wait() {
    asm volatile("cp.async.wait_group %0;" :: "n"(N) : "memory");
}
__device__ __forceinline__ void ldmx4(uint32_t& r0, uint32_t& r1, uint32_t& r2, uint32_t& r3,
                                      uint32_t addr) {
    asm volatile("ldmatrix.sync.aligned.m8n8.x4.shared.b16 {%0,%1,%2,%3}, [%4];"
                 : "=r"(r0), "=r"(r1), "=r"(r2), "=r"(r3) : "r"(addr));
}
__device__ __forceinline__ void mma16816(float& c0, float& c1, float& c2, float& c3,
                                         uint32_t a0, uint32_t a1, uint32_t a2, uint32_t a3,
                                         uint32_t b0, uint32_t b1) {
    asm volatile("mma.sync.aligned.m16n8k16.row.col.f32.bf16.bf16.f32 "
                 "{%0,%1,%2,%3}, {%4,%5,%6,%7}, {%8,%9}, {%0,%1,%2,%3};"
                 : "+f"(c0), "+f"(c1), "+f"(c2), "+f"(c3)
                 : "r"(a0), "r"(a1), "r"(a2), "r"(a3), "r"(b0), "r"(b1));
}
__device__ __forceinline__ void mma1688tf(float& c0, float& c1, float& c2, float& c3,
                                          uint32_t a0, uint32_t a1, uint32_t a2, uint32_t a3,
                                          uint32_t b0, uint32_t b1) {
    asm volatile("mma.sync.aligned.m16n8k8.row.col.f32.tf32.tf32.f32 "
                 "{%0,%1,%2,%3}, {%4,%5,%6,%7}, {%8,%9}, {%0,%1,%2,%3};"
                 : "+f"(c0), "+f"(c1), "+f"(c2), "+f"(c3)
                 : "r"(a0), "r"(a1), "r"(a2), "r"(a3), "r"(b0), "r"(b1));
}
__device__ __forceinline__ void cvt_tf32(uint32_t& x) {
    asm volatile("cvt.rna.tf32.f32 %0, %0;" : "+r"(x));
}
__device__ __forceinline__ uint32_t pack_bf2(float a, float b) {
    __nv_bfloat162 h = __floats2bfloat162_rn(a, b);
    return *(uint32_t*)&h;
}
__device__ __forceinline__ float2 unpack_bf2(uint32_t u) {
    __nv_bfloat162 h = *(__nv_bfloat162*)&u;
    return make_float2(__bfloat162float(h.x), __bfloat162float(h.y));
}

// fast-math helpers (MUFU-backed approximations)
__device__ __forceinline__ float fast_tanh(float x) {
    float y; asm("tanh.approx.f32 %0, %1;" : "=f"(y) : "f"(x)); return y;
}
__device__ __forceinline__ float fast_ex2(float x) {
    float y; asm("ex2.approx.f32 %0, %1;" : "=f"(y) : "f"(x)); return y;
}
__device__ __forceinline__ float fast_lg2(float x) {
    float y; asm("lg2.approx.f32 %0, %1;" : "=f"(y) : "f"(x)); return y;
}
__device__ __forceinline__ float fast_rcp(float x) {
    float y; asm("rcp.approx.f32 %0, %1;" : "=f"(y) : "f"(x)); return y;
}
#define LOG2E_F 1.4426950408889634f
#define LN2_F   0.6931471805599453f
__device__ __forceinline__ float fast_sigmoid(float x) {
    return fast_rcp(1.f + fast_ex2(-LOG2E_F * x));
}
__device__ __forceinline__ float fast_log(float x) {
    return LN2_F * fast_lg2(x);
}

// ================= mma.sync bf16 NT GEMM for Cf/Cb (3-stage, 2 CTA/SM) =================
#define CG_ST    3
#define CG_KC    64
#define CG_NCH   8
#define CG_STAGE 16384
#define CG_SMEM  (CG_ST * 2 * CG_STAGE) // 98304

__device__ __forceinline__ void cg_load_chunk(const __nv_bfloat16* Ag, const __nv_bfloat16* Bg,
                                              int c, uint32_t sA, uint32_t sB, int tid) {
    int k0 = c * CG_KC;
#pragma unroll
    for (int f = tid; f < 1024; f += 256) {
        int row = f >> 3, seg = f & 7;
        cpasync16(sA + swz128(row * 128 + seg * 16), Ag + (size_t)row * 512 + k0 + seg * 8);
    }
#pragma unroll
    for (int f = tid; f < 1024; f += 256) {
        int row = f >> 3, seg = f & 7;
        cpasync16(sB + swz128(row * 128 + seg * 16), Bg + (size_t)row * 512 + k0 + seg * 8);
    }
}

__global__ __launch_bounds__(256, 2) void c_gemm_mma() {
    extern __shared__ char smem_raw[];
    uint32_t sb = smem_u32(smem_raw);
    int tid = threadIdx.x;
    int wid = tid >> 5, lane = tid & 31;
    int wm = wid >> 2, wn = wid & 3;

    int z = blockIdx.z, dir = z >> 5, bh = z & 31;
    const __nv_bfloat16* Ag = (dir ? g_A1b  : g_A0b ) + (size_t)bh * NM + (size_t)blockIdx.y * 128 * 512;
    const __nv_bfloat16* Bg = (dir ? g_A0Tb : g_A1Tb) + (size_t)bh * NM + (size_t)blockIdx.x * 128 * 512;
    __nv_bfloat16*       Cg = (dir ? g_Cbb  : g_Cfb ) + (size_t)bh * NM;

#pragma unroll
    for (int c = 0; c < 2; c++) {
        uint32_t st = sb + (uint32_t)c * 2 * CG_STAGE;
        cg_load_chunk(Ag, Bg, c, st, st + CG_STAGE, tid);
        cp_commit();
    }

    float acc[4][4][4];
#pragma unroll
    for (int i = 0; i < 4; i++)
#pragma unroll
        for (int j = 0; j < 4; j++)
#pragma unroll
            for (int k = 0; k < 4; k++) acc[i][j][k] = 0.f;

    int rowA  = wm * 64 + (lane & 15);
    int hiA   = lane >> 4;
    int sxA   = rowA & 7;
    int nB    = wn * 32 + (lane & 7) + ((lane >> 4) << 3);
    int ksegB = (lane >> 3) & 1;
    int sxB   = nB & 7;

    for (int c = 0; c < CG_NCH; c++) {
        if (c + 2 < CG_NCH) {
            uint32_t st = sb + (uint32_t)((c + 2) % CG_ST) * 2 * CG_STAGE;
            cg_load_chunk(Ag, Bg, c + 2, st, st + CG_STAGE, tid);
            cp_commit();
            cp_wait<2>();
        } else if (c + 1 < CG_NCH) {
            cp_wait<1>();
        } else {
            cp_wait<0>();
        }
        __syncthreads();
        uint32_t sA = sb + (uint32_t)(c % CG_ST) * 2 * CG_STAGE;
        uint32_t sBm = sA + CG_STAGE;
#pragma unroll
        for (int ks = 0; ks < 4; ks++) {
            uint32_t a[4][4];
#pragma unroll
            for (int mf = 0; mf < 4; mf++) {
                uint32_t addr = sA + rowA * 128 + mf * 2048 + 16 * ((2 * ks + hiA) ^ sxA);
                ldmx4(a[mf][0], a[mf][1], a[mf][2], a[mf][3], addr);
            }
            uint32_t b[2][4];
#pragma unroll
            for (int nf = 0; nf < 2; nf++) {
                uint32_t addr = sBm + nB * 128 + nf * 2048 + 16 * ((2 * ks + ksegB) ^ sxB);
                ldmx4(b[nf][0], b[nf][1], b[nf][2], b[nf][3], addr);
            }
#pragma unroll
            for (int mf = 0; mf < 4; mf++)
#pragma unroll
                for (int nf = 0; nf < 2; nf++) {
                    mma16816(acc[mf][2*nf  ][0], acc[mf][2*nf  ][1], acc[mf][2*nf  ][2], acc[mf][2*nf  ][3],
                             a[mf][0], a[mf][1], a[mf][2], a[mf][3], b[nf][0], b[nf][1]);
                    mma16816(acc[mf][2*nf+1][0], acc[mf][2*nf+1][1], acc[mf][2*nf+1][2], acc[mf][2*nf+1][3],
                             a[mf][0], a[mf][1], a[mf][2], a[mf][3], b[nf][2], b[nf][3]);
                }
        }
        __syncthreads();
    }

    int m0 = blockIdx.y * 128, n0 = blockIdx.x * 128;
#pragma unroll
    for (int mf = 0; mf < 4; mf++) {
        int r = m0 + wm * 64 + mf * 16 + (lane >> 2);
#pragma unroll
        for (int nfr = 0; nfr < 4; nfr++) {
            int col = n0 + wn * 32 + nfr * 8 + 2 * (lane & 3);
            *(uint32_t*)&Cg[(size_t)r * 512 + col]       = pack_bf2(acc[mf][nfr][0], acc[mf][nfr][1]);
            *(uint32_t*)&Cg[(size_t)(r + 8) * 512 + col] = pack_bf2(acc[mf][nfr][2], acc[mf][nfr][3]);
        }
    }
}

// ================= tf32 mma.sync NT GEMM core (128x128, 3-stage) =================
#define TF_STAGE 16384
#define TF_SMEM_S (2 * 2 * TF_STAGE)     // 65536 (K=64 user: s_tf32)

__device__ __forceinline__ void tf_load_chunk(const float* Ag, const float* Bg,
                                              int lda, int ldb, int c,
                                              uint32_t sA, uint32_t sB, int tid) {
    int k0 = c * 32;
#pragma unroll
    for (int f = tid; f < 1024; f += 256) {
        int row = f >> 3, seg = f & 7;
        cpasync16(sA + swz128(row * 128 + seg * 16), Ag + (size_t)row * lda + k0 + seg * 4);
    }
#pragma unroll
    for (int f = tid; f < 1024; f += 256) {
        int row = f >> 3, seg = f & 7;
        cpasync16(sB + swz128(row * 128 + seg * 16), Bg + (size_t)row * ldb + k0 + seg * 4);
    }
}

__device__ __forceinline__ void tf32_core(const float* Ag, const float* Bg,
                                          int lda, int ldb, int nch,
                                          uint32_t sb, int tid, float acc[4][4][4]) {
    int lane = tid & 31, wid = tid >> 5;
    int wm = wid >> 2, wn = wid & 3;

    int npro = nch < 2 ? nch : 2;
    for (int c = 0; c < npro; c++) {
        uint32_t st = sb + (uint32_t)c * 2 * TF_STAGE;
        tf_load_chunk(Ag, Bg, lda, ldb, c, st, st + TF_STAGE, tid);
        cp_commit();
    }

    int rA_off = wm * 64 + (lane & 7) + ((lane >> 3) & 1) * 8;
    int csA    = lane >> 4;
    int rB_off = wn * 32 + (lane & 7) + (lane >> 4) * 8;
    int ksB    = (lane >> 3) & 1;

    for (int c = 0; c < nch; c++) {
        if (c + 2 < nch) {
            uint32_t st = sb + (uint32_t)((c + 2) % 3) * 2 * TF_STAGE;
            tf_load_chunk(Ag, Bg, lda, ldb, c + 2, st, st + TF_STAGE, tid);
            cp_commit();
            cp_wait<2>();
        } else if (c + 1 < nch) {
            cp_wait<1>();
        } else {
            cp_wait<0>();
        }
        __syncthreads();
        uint32_t sA = sb + (uint32_t)(c % 3) * 2 * TF_STAGE;
        uint32_t sB = sA + TF_STAGE;
#pragma unroll
        for (int ks = 0; ks < 4; ks++) {
            uint32_t a[4][4];
#pragma unroll
            for (int mf = 0; mf < 4; mf++) {
                int row = rA_off + mf * 16;
                uint32_t addr = sA + row * 128 + 16 * ((2 * ks + csA) ^ (row & 7));
                ldmx4(a[mf][0], a[mf][1], a[mf][2], a[mf][3], addr);
                cvt_tf32(a[mf][0]); cvt_tf32(a[mf][1]); cvt_tf32(a[mf][2]); cvt_tf32(a[mf][3]);
            }
            uint32_t b[2][4];
#pragma unroll
            for (int p = 0; p < 2; p++) {
                int row = rB_off + p * 16;
                uint32_t addr = sB + row * 128 + 16 * ((2 * ks + ksB) ^ (row & 7));
                ldmx4(b[p][0], b[p][1], b[p][2], b[p][3], addr);
                cvt_tf32(b[p][0]); cvt_tf32(b[p][1]); cvt_tf32(b[p][2]); cvt_tf32(b[p][3]);
            }
#pragma unroll
            for (int mf = 0; mf < 4; mf++)
#pragma unroll
                for (int p = 0; p < 2; p++) {
                    mma1688tf(acc[mf][2*p  ][0], acc[mf][2*p  ][1], acc[mf][2*p  ][2], acc[mf][2*p  ][3],
                              a[mf][0], a[mf][1], a[mf][2], a[mf][3], b[p][0], b[p][1]);
                    mma1688tf(acc[mf][2*p+1][0], acc[mf][2*p+1][1], acc[mf][2*p+1][2], acc[mf][2*p+1][3],
                              a[mf][0], a[mf][1], a[mf][2], a[mf][3], b[p][2], b[p][3]);
                }
        }
        __syncthreads();
    }
}

// ================= 64x128-tile tf32 core pieces (proj/qkv shared) =================
#define PJ_ST_A  8192                    // 64 rows * 128B
#define PJ_ST_B  16384                   // 128 rows * 128B
#define PJ_STAGE (PJ_ST_A + PJ_ST_B)     // 24576
#define PJ_SMEM  (3 * PJ_STAGE)          // 73728

__device__ __forceinline__ void pj_load_chunk(const float* Ag, const float* Bg, int c,
                                              uint32_t sA, uint32_t sB, int tid) {
    int k0 = c * 32;
#pragma unroll
    for (int f = tid; f < 512; f += 256) {
        int row = f >> 3, seg = f & 7;
        cpasync16(sA + swz128(row * 128 + seg * 16), Ag + (size_t)row * 512 + k0 + seg * 4);
    }
#pragma unroll
    for (int f = tid; f < 1024; f += 256) {
        int row = f >> 3, seg = f & 7;
        cpasync16(sB + swz128(row * 128 + seg * 16), Bg + (size_t)row * 512 + k0 + seg * 4);
    }
}

// body: 64x128 output tile, warps 2(m) x 4(n), K=512
__device__ __forceinline__ void pj_core(const float* Ag, const float* Bg,
                                        uint32_t sb, int tid, float acc[2][4][4]) {
    int lane = tid & 31, wid = tid >> 5;
    int wm = wid >> 2, wn = wid & 3;

#pragma unroll
    for (int c = 0; c < 2; c++) {
        uint32_t st = sb + (uint32_t)c * PJ_STAGE;
        pj_load_chunk(Ag, Bg, c, st, st + PJ_ST_A, tid);
        cp_commit();
    }

    int rA_off = wm * 32 + (lane & 7) + ((lane >> 3) & 1) * 8;
    int csA    = lane >> 4;
    int rB_off = wn * 32 + (lane & 7) + (lane >> 4) * 8;
    int ksB    = (lane >> 3) & 1;

    for (int c = 0; c < 16; c++) {
        if (c + 2 < 16) {
            uint32_t st = sb + (uint32_t)((c + 2) % 3) * PJ_STAGE;
            pj_load_chunk(Ag, Bg, c + 2, st, st + PJ_ST_A, tid);
            cp_commit();
            cp_wait<2>();
        } else if (c + 1 < 16) {
            cp_wait<1>();
        } else {
            cp_wait<0>();
        }
        __syncthreads();
        uint32_t sA = sb + (uint32_t)(c % 3) * PJ_STAGE;
        uint32_t sB = sA + PJ_ST_A;
#pragma unroll
        for (int ks = 0; ks < 4; ks++) {
            uint32_t a[2][4];
#pragma unroll
            for (int mf = 0; mf < 2; mf++) {
                int row = rA_off + mf * 16;
                uint32_t addr = sA + row * 128 + 16 * ((2 * ks + csA) ^ (row & 7));
                ldmx4(a[mf][0], a[mf][1], a[mf][2], a[mf][3], addr);
                cvt_tf32(a[mf][0]); cvt_tf32(a[mf][1]); cvt_tf32(a[mf][2]); cvt_tf32(a[mf][3]);
            }
            uint32_t b[2][4];
#pragma unroll
            for (int p = 0; p < 2; p++) {
                int row = rB_off + p * 16;
                uint32_t addr = sB + row * 128 + 16 * ((2 * ks + ksB) ^ (row & 7));
                ldmx4(b[p][0], b[p][1], b[p][2], b[p][3], addr);
                cvt_tf32(b[p][0]); cvt_tf32(b[p][1]); cvt_tf32(b[p][2]); cvt_tf32(b[p][3]);
            }
#pragma unroll
            for (int mf = 0; mf < 2; mf++)
#pragma unroll
                for (int p = 0; p < 2; p++) {
                    mma1688tf(acc[mf][2*p  ][0], acc[mf][2*p  ][1], acc[mf][2*p  ][2], acc[mf][2*p  ][3],
                              a[mf][0], a[mf][1], a[mf][2], a[mf][3], b[p][0], b[p][1]);
                    mma1688tf(acc[mf][2*p+1][0], acc[mf][2*p+1][1], acc[mf][2*p+1][2], acc[mf][2*p+1][3],
                              a[mf][0], a[mf][1], a[mf][2], a[mf][3], b[p][2], b[p][3]);
                }
        }
        __syncthreads();
    }
}

// ---------------- 1) QKV GEMM (tf32, 64x128 tiles, 768 CTAs) ----------------
__global__ __launch_bounds__(256, 2) void qkv_tf32(const float* __restrict__ x,
                                                   const float* __restrict__ w0,
                                                   const float* __restrict__ w1) {
    extern __shared__ char smem_raw[];
    uint32_t sb = smem_u32(smem_raw);
    int tid = threadIdx.x, lane = tid & 31, wid = tid >> 5;
    int wm = wid >> 2, wn = wid & 3;
    int set = blockIdx.z;
    const float* W = set ? w1 : w0;
    int m0 = blockIdx.y * 64, n0 = blockIdx.x * 128;

    float acc[2][4][4];
#pragma unroll
    for (int i = 0; i < 2; i++)
#pragma unroll
        for (int j = 0; j < 4; j++)
#pragma unroll
            for (int k = 0; k < 4; k++) acc[i][j][k] = 0.f;

    pj_core(x + (size_t)m0 * 512, W + (size_t)n0 * 512, sb, tid, acc);

    float* q = set ? g_q1 : g_q0;
    float* kk = set ? g_k1 : g_k0;
    float* v = set ? g_v1 : g_v0;
#pragma unroll
    for (int mf = 0; mf < 2; mf++) {
        int r = m0 + wm * 32 + mf * 16 + (lane >> 2);
#pragma unroll
        for (int half = 0; half < 2; half++) {
            int rr = r + half * 8;
            int b = rr >> 9, n = rr & 511;
#pragma unroll
            for (int nf = 0; nf < 4; nf++) {
                int col = n0 + wn * 32 + nf * 8 + 2 * (lane & 3);
                int t = col >> 9, rem = col & 511, h = rem >> 6, d = rem & 63;
                float* dst = (t == 0) ? q : (t == 1) ? kk : v;
                float2 val = half ? make_float2(acc[mf][nf][2], acc[mf][nf][3])
                                  : make_float2(acc[mf][nf][0], acc[mf][nf][1]);
                *(float2*)&dst[(((size_t)b*8 + h)*512 + n)*64 + d] = val;
            }
        }
    }
}

// ---------------- 3) S = scale * q @ k^T; writes S fp32, S bf16, S^T bf16 ----------
__global__ __launch_bounds__(256, 2) void s_tf32() {
    extern __shared__ char smem_raw[];
    uint32_t sb = smem_u32(smem_raw);
    int tid = threadIdx.x, lane = tid & 31, wid = tid >> 5;
    int wm = wid >> 2, wn = wid & 3;
    int z = blockIdx.z, pair = z >> 5, bh = z & 31;
    const float* Q = (pair ? g_q1 : g_q0) + (size_t)bh * NN_ * DK;
    const float* K = (pair ? g_k1 : g_k0) + (size_t)bh * NN_ * DK;
    float* C  = (pair ? g_S1  : g_S0 ) + (size_t)bh * NM;
    __nv_bfloat16* Cb  = (pair ? g_S1b  : g_S0b ) + (size_t)bh * NM;
    __nv_bfloat16* CTb = (pair ? g_S1Tb : g_S0Tb) + (size_t)bh * NM;
    int m0 = blockIdx.y * 128, n0 = blockIdx.x * 128;

    float acc[4][4][4];
#pragma unroll
    for (int i = 0; i < 4; i++)
#pragma unroll
        for (int j = 0; j < 4; j++)
#pragma unroll
            for (int k = 0; k < 4; k++) acc[i][j][k] = 0.f;

    tf32_core(Q + (size_t)m0 * 64, K + (size_t)n0 * 64, 64, 64, 2, sb, tid, acc);

#pragma unroll
    for (int mf = 0; mf < 4; mf++) {
        int r = m0 + wm * 64 + mf * 16 + (lane >> 2);
#pragma unroll
        for (int nf = 0; nf < 4; nf++) {
            int col = n0 + wn * 32 + nf * 8 + 2 * (lane & 3);
            float v0 = 0.125f * acc[mf][nf][0], v1 = 0.125f * acc[mf][nf][1];
            float v2 = 0.125f * acc[mf][nf][2], v3 = 0.125f * acc[mf][nf][3];
            *(float2*)&C[(size_t)r * 512 + col]        = make_float2(v0, v1);
            *(float2*)&C[(size_t)(r + 8) * 512 + col]  = make_float2(v2, v3);
            *(uint32_t*)&Cb[(size_t)r * 512 + col]       = pack_bf2(v0, v1);
            *(uint32_t*)&Cb[(size_t)(r + 8) * 512 + col] = pack_bf2(v2, v3);
        }
    }

    float* tile = (float*)smem_raw;
#pragma unroll
    for (int hp = 0; hp < 2; hp++) {
        __syncthreads();
#pragma unroll
        for (int mf = 0; mf < 4; mf++) {
            int r = wm * 64 + mf * 16 + (lane >> 2);
#pragma unroll
            for (int nf = 0; nf < 4; nf++) {
                int cbase = wn * 32 + nf * 8 + 2 * (lane & 3);
                if ((cbase >> 6) == hp) {
                    int lc = cbase & 63;
                    tile[(lc    ) * 132 + r    ] = 0.125f * acc[mf][nf][0];
                    tile[(lc + 1) * 132 + r    ] = 0.125f * acc[mf][nf][1];
                    tile[(lc    ) * 132 + r + 8] = 0.125f * acc[mf][nf][2];
                    tile[(lc + 1) * 132 + r + 8] = 0.125f * acc[mf][nf][3];
                }
            }
        }
        __syncthreads();
#pragma unroll
        for (int f = tid; f < 2048; f += 256) {
            int c = f >> 5, seg = f & 31;
            float4 val = *(float4*)&tile[c * 132 + seg * 4];
            uint2 pk;
            pk.x = pack_bf2(val.x, val.y);
            pk.y = pack_bf2(val.z, val.w);
            *(uint2*)&CTb[(size_t)(n0 + hp * 64 + c) * 512 + m0 + seg * 4] = pk;
        }
    }
}

// ---------------- 9) final projection (64x128 tiles) ----------------
__global__ __launch_bounds__(256, 2) void proj_tf32(const float* __restrict__ wp,
                                                    float* __restrict__ out) {
    extern __shared__ char smem_raw[];
    uint32_t sb = smem_u32(smem_raw);
    int tid = threadIdx.x, lane = tid & 31, wid = tid >> 5;
    int wm = wid >> 2, wn = wid & 3;
    int m0 = blockIdx.y * 64, n0 = blockIdx.x * 128;

    float acc[2][4][4];
#pragma unroll
    for (int i = 0; i < 2; i++)
#pragma unroll
        for (int j = 0; j < 4; j++)
#pragma unroll
            for (int k = 0; k < 4; k++) acc[i][j][k] = 0.f;

    pj_core(g_attn + (size_t)m0 * 512, wp + (size_t)n0 * 512, sb, tid, acc);

#pragma unroll
    for (int mf = 0; mf < 2; mf++) {
        int r = m0 + wm * 32 + mf * 16 + (lane >> 2);
#pragma unroll
        for (int nf = 0; nf < 4; nf++) {
            int col = n0 + wn * 32 + nf * 8 + 2 * (lane & 3);
            *(float2*)&out[(size_t)r * 512 + col]       = make_float2(acc[mf][nf][0], acc[mf][nf][1]);
            *(float2*)&out[(size_t)(r + 8) * 512 + col] = make_float2(acc[mf][nf][2], acc[mf][nf][3]);
        }
    }
}

// ================= 8) mv — 64x64 tiles (256 CTAs) =================
#define MV_ST_A  8192
#define MV_ST_B  8192
#define MV_STAGE (MV_ST_A + MV_ST_B)     // 16384
#define MV_SMEM  (3 * MV_STAGE)          // 49152

__device__ __forceinline__ void mv_load_chunk(const float* Ag, const float* Bg, int c,
                                              uint32_t sA, uint32_t sB, int tid) {
    int k0 = c * 32;
#pragma unroll
    for (int f = tid; f < 512; f += 256) {
        int row = f >> 3, seg = f & 7;
        cpasync16(sA + swz128(row * 128 + seg * 16), Ag + (size_t)row * 512 + k0 + seg * 4);
    }
#pragma unroll
    for (int f = tid; f < 512; f += 256) {
        int row = f >> 3, seg = f & 7;
        cpasync16(sB + swz128(row * 128 + seg * 16), Bg + (size_t)row * 512 + k0 + seg * 4);
    }
}

__global__ __launch_bounds__(256, 2) void mv_tf32() {
    extern __shared__ char smem_raw[];
    uint32_t sb = smem_u32(smem_raw);
    int tid = threadIdx.x, lane = tid & 31, wid = tid >> 5;
    int wm = wid >> 2, wn = wid & 3;
    int z = blockIdx.z;
    int m0 = blockIdx.y * 64;

    const float* Ag = g_M  + (size_t)z * NM + (size_t)m0 * 512;
    const float* Bg = g_vT + (size_t)z * DK * 512;

    float acc[2][2][4];
#pragma unroll
    for (int i = 0; i < 2; i++)
#pragma unroll
        for (int j = 0; j < 2; j++)
#pragma unroll
            for (int k = 0; k < 4; k++) acc[i][j][k] = 0.f;

#pragma unroll
    for (int c = 0; c < 2; c++) {
        uint32_t st = sb + (uint32_t)c * MV_STAGE;
        mv_load_chunk(Ag, Bg, c, st, st + MV_ST_A, tid);
        cp_commit();
    }

    int rA_off = wm * 32 + (lane & 7) + ((lane >> 3) & 1) * 8;
    int csA    = lane >> 4;
    int rB_off = wn * 16 + (lane & 7) + (lane >> 4) * 8;
    int ksB    = (lane >> 3) & 1;

    for (int c = 0; c < 16; c++) {
        if (c + 2 < 16) {
            uint32_t st = sb + (uint32_t)((c + 2) % 3) * MV_STAGE;
            mv_load_chunk(Ag, Bg, c + 2, st, st + MV_ST_A, tid);
            cp_commit();
            cp_wait<2>();
        } else if (c + 1 < 16) {
            cp_wait<1>();
        } else {
            cp_wait<0>();
        }
        __syncthreads();
        uint32_t sA = sb + (uint32_t)(c % 3) * MV_STAGE;
        uint32_t sB = sA + MV_ST_A;
#pragma unroll
        for (int ks = 0; ks < 4; ks++) {
            uint32_t a[2][4];
#pragma unroll
            for (int mf = 0; mf < 2; mf++) {
                int row = rA_off + mf * 16;
                uint32_t addr = sA + row * 128 + 16 * ((2 * ks + csA) ^ (row & 7));
                ldmx4(a[mf][0], a[mf][1], a[mf][2], a[mf][3], addr);
                cvt_tf32(a[mf][0]); cvt_tf32(a[mf][1]); cvt_tf32(a[mf][2]); cvt_tf32(a[mf][3]);
            }
            uint32_t b0, b1, b2, b3;
            {
                int row = rB_off;
                uint32_t addr = sB + row * 128 + 16 * ((2 * ks + ksB) ^ (row & 7));
                ldmx4(b0, b1, b2, b3, addr);
                cvt_tf32(b0); cvt_tf32(b1); cvt_tf32(b2); cvt_tf32(b3);
            }
#pragma unroll
            for (int mf = 0; mf < 2; mf++) {
                mma1688tf(acc[mf][0][0], acc[mf][0][1], acc[mf][0][2], acc[mf][0][3],
                          a[mf][0], a[mf][1], a[mf][2], a[mf][3], b0, b1);
                mma1688tf(acc[mf][1][0], acc[mf][1][1], acc[mf][1][2], acc[mf][1][3],
                          a[mf][0], a[mf][1], a[mf][2], a[mf][3], b2, b3);
            }
        }
        __syncthreads();
    }

    int b = z >> 3, h = z & 7;
#pragma unroll
    for (int mf = 0; mf < 2; mf++) {
        int n = m0 + wm * 32 + mf * 16 + (lane >> 2);
        float sc0 = 1.f / (g_rowsum[z * 512 + n] + EPSF);
        float sc1 = 1.f / (g_rowsum[z * 512 + n + 8] + EPSF);
#pragma unroll
        for (int nf = 0; nf < 2; nf++) {
            int d = wn * 16 + nf * 8 + 2 * (lane & 3);
            *(float2*)&g_attn[((size_t)b * 512 + n) * 512 + h * 64 + d] =
                make_float2(acc[mf][nf][0] * sc0, acc[mf][nf][1] * sc0);
            *(float2*)&g_attn[((size_t)b * 512 + n + 8) * 512 + h * 64 + d] =
                make_float2(acc[mf][nf][2] * sc1, acc[mf][nf][3] * sc1);
        }
    }
}

// ---------------- 2) v mix + transpose: vT[bh][d][n], d = 0..63 ----------------
__global__ void vmix_k(const float* __restrict__ cl) {
    __shared__ float t[32][33];
    float a = fast_sigmoid(cl[0]);
    int bh = blockIdx.z;
    int d0 = blockIdx.x * 32, n0 = blockIdx.y * 32;
    const float* v0 = g_v0 + (size_t)bh * NN_ * DK;
    const float* v1 = g_v1 + (size_t)bh * NN_ * DK;
    float* vt = g_vT + (size_t)bh * DK * 512;
    int tx = threadIdx.x, ty = threadIdx.y;
#pragma unroll
    for (int i = 0; i < 32; i += 8) {
        size_t idx = (size_t)(n0 + ty + i) * 64 + d0 + tx;
        t[ty + i][tx] = (1.f - a) * v0[idx] + a * v1[idx];
    }
    __syncthreads();
#pragma unroll
    for (int i = 0; i < 32; i += 8)
        vt[(size_t)(d0 + ty + i) * 512 + n0 + tx] = t[tx][ty + i];
}

// ---------------- 4) warp-per-row softmax (A0 fp32+bf16; A1 bf16 only) ----------------
__global__ void softmax_k() {
    int gw = blockIdx.x * 8 + (threadIdx.x >> 5);
    int pair = gw >> 14, r = gw & 16383;
    const float* src = (pair ? g_S1 : g_S0) + (size_t)r * 512;
    __nv_bfloat16* dstb = (pair ? g_A1b : g_A0b) + (size_t)r * 512;
    int lane = threadIdx.x & 31;

    float4 v[4];
#pragma unroll
    for (int q = 0; q < 4; q++) v[q] = ((const float4*)src)[q * 32 + lane];

    float mx = -1e30f;
#pragma unroll
    for (int q = 0; q < 4; q++)
        mx = fmaxf(mx, fmaxf(fmaxf(v[q].x, v[q].y), fmaxf(v[q].z, v[q].w)));
#pragma unroll
    for (int s = 16; s > 0; s >>= 1) mx = fmaxf(mx, __shfl_xor_sync(0xffffffffu, mx, s));

    float sum = 0.f;
#pragma unroll
    for (int q = 0; q < 4; q++) {
        v[q].x = expf(v[q].x - mx);  v[q].y = expf(v[q].y - mx);
        v[q].z = expf(v[q].z - mx);  v[q].w = expf(v[q].w - mx);
        sum += v[q].x + v[q].y + v[q].z + v[q].w;
    }
#pragma unroll
    for (int s = 16; s > 0; s >>= 1) sum += __shfl_xor_sync(0xffffffffu, sum, s);
    float inv = 1.f / sum;

    float* dst0 = g_A0 + (size_t)r * 512;
#pragma unroll
    for (int q = 0; q < 4; q++) {
        float4 o = make_float4(v[q].x * inv, v[q].y * inv, v[q].z * inv, v[q].w * inv);
        if (pair == 0) ((float4*)dst0)[q * 32 + lane] = o;
        uint2 pk;
        pk.x = pack_bf2(o.x, o.y);
        pk.y = pack_bf2(o.z, o.w);
        ((uint2*)dstb)[q * 32 + lane] = pk;
    }
}

// ---------------- 5) tiled transposes: A0b,A1b (bf16 src) -> bf16 transposed ----------------
__global__ void transpose_k() {
    __shared__ float tile[32][33];
    int z = blockIdx.z, sel = z >> 5, bh = z & 31;
    const __nv_bfloat16* src = (sel == 0 ? g_A0b : g_A1b) + (size_t)bh * NM;
    __nv_bfloat16* dstb = (sel == 0 ? g_A0Tb : g_A1Tb) + (size_t)bh * NM;
    int x0 = blockIdx.x * 32, y0 = blockIdx.y * 32;
    int tx = threadIdx.x, ty = threadIdx.y;
#pragma unroll
    for (int i = 0; i < 32; i += 8)
        tile[ty + i][tx] = __bfloat162float(src[(size_t)(y0 + ty + i) * 512 + x0 + tx]);
    __syncthreads();
#pragma unroll
    for (int i = 0; i < 32; i += 8)
        dstb[(size_t)(x0 + ty + i) * 512 + y0 + tx] = __float2bfloat16(tile[tx][ty + i]);
}

// ---------------- 7) gate + combine (vectorized: 2 elems/thread, 1 pass) ----------
__global__ void gate_k(const float* __restrict__ c1w, const float* __restrict__ c1b,
                       const float* __restrict__ c2w, const float* __restrict__ c2b) {
    int row = blockIdx.x;
    size_t base = (size_t)row * 512;
    __shared__ float sw1[96], sb1[16], sw2[64], sb2[4];
    int tid = threadIdx.x;
    if (tid < 96)       sw1[tid]       = c1w[tid];
    else if (tid < 112) sb1[tid - 96]  = c1b[tid - 96];
    else if (tid < 176) sw2[tid - 112] = c2w[tid - 112];
    else if (tid < 180) sb2[tid - 176] = c2b[tid - 176];
    __syncthreads();

    int m = tid * 2;
    float2 f0v = unpack_bf2(*(const uint32_t*)&g_S0b [base + m]);
    float2 f1v = unpack_bf2(*(const uint32_t*)&g_S1b [base + m]);
    float2 f2v = unpack_bf2(*(const uint32_t*)&g_S0Tb[base + m]);
    float2 f3v = unpack_bf2(*(const uint32_t*)&g_S1Tb[base + m]);
    float2 cfv = unpack_bf2(*(const uint32_t*)&g_Cfb [base + m]);
    float2 cbv = unpack_bf2(*(const uint32_t*)&g_Cbb [base + m]);
    float2 a0v = *(const float2*)&g_A0[base + m];
    float2 a1v = unpack_bf2(*(const uint32_t*)&g_A1b[base + m]);

    float f0a[2] = { f0v.x, f0v.y }, f1a[2] = { f1v.x, f1v.y };
    float f2a[2] = { f2v.x, f2v.y }, f3a[2] = { f3v.x, f3v.y };
    float cfa[2] = { cfv.x, cfv.y }, cba[2] = { cbv.x, cbv.y };
    float a0a[2] = { a0v.x, a0v.y }, a1a[2] = { a1v.x, a1v.y };
    float mv[2];
    float lsum = 0.f;
#pragma unroll
    for (int e = 0; e < 2; e++) {
        float f4 = fast_log(cfa[e] + EPSF);
        float f5 = fast_log(cba[e] + EPSF);
        float a2[4] = { sb2[0], sb2[1], sb2[2], sb2[3] };
#pragma unroll
        for (int o = 0; o < 16; o++) {
            float h = sb1[o] + sw1[o*6+0]*f0a[e] + sw1[o*6+1]*f1a[e] + sw1[o*6+2]*f2a[e]
                             + sw1[o*6+3]*f3a[e] + sw1[o*6+4]*f4     + sw1[o*6+5]*f5;
            float u = 0.7978845608028654f * (h + 0.044715f * h * h * h);
            float g = 0.5f * h * (1.f + fast_tanh(u));
            a2[0] += sw2[ 0 + o] * g;
            a2[1] += sw2[16 + o] * g;
            a2[2] += sw2[32 + o] * g;
            a2[3] += sw2[48 + o] * g;
        }
        float G0 = fast_sigmoid(a2[0]);
        float G1 = fast_sigmoid(a2[1]);
        float G2 = fast_sigmoid(a2[2]);
        float G3 = fast_sigmoid(a2[3]);
        float aand = a0a[e] * a1a[e];
        float aor  = a0a[e] + a1a[e] - aand;
        float anot = a0a[e] * (1.f - 0.5f * a1a[e]);
        mv[e] = a0a[e] + G0*aand + G1*aor + G2*anot + G3*cfa[e];
        lsum += mv[e];
    }
    *(float2*)&g_M[base + m] = make_float2(mv[0], mv[1]);

    __shared__ float red[256];
    red[tid] = lsum;
    __syncthreads();
    for (int s = 128; s > 0; s >>= 1) { if (tid < s) red[tid] += red[tid+s]; __syncthreads(); }
    if (tid == 0) g_rowsum[row] = red[0];
}

// ---------------- launch ----------------
extern "C" void kernel_launch(void* const* d_in, const int* in_sizes, int n_in,
                              void* d_out, int out_size) {
    const float* x    = (const float*)d_in[0];
    const float* w0   = (const float*)d_in[1];
    const float* w1   = (const float*)d_in[2];
    const float* c1w  = (const float*)d_in[3];
    const float* c1b  = (const float*)d_in[4];
    const float* c2w  = (const float*)d_in[5];
    const float* c2b  = (const float*)d_in[6];
    const float* wp   = (const float*)d_in[7];
    const float* cl   = (const float*)d_in[8];
    float* out = (float*)d_out;

    cudaFuncSetAttribute(c_gemm_mma, cudaFuncAttributeMaxDynamicSharedMemorySize, CG_SMEM);
    cudaFuncSetAttribute(qkv_tf32,   cudaFuncAttributeMaxDynamicSharedMemorySize, PJ_SMEM);
    cudaFuncSetAttribute(s_tf32,     cudaFuncAttributeMaxDynamicSharedMemorySize, TF_SMEM_S);
    cudaFuncSetAttribute(mv_tf32,    cudaFuncAttributeMaxDynamicSharedMemorySize, MV_SMEM);
    cudaFuncSetAttribute(proj_tf32,  cudaFuncAttributeMaxDynamicSharedMemorySize, PJ_SMEM);

    qkv_tf32   <<<dim3(12, 32, 2), 256, PJ_SMEM>>>(x, w0, w1);
    vmix_k     <<<dim3(2, 16, 32), dim3(32, 8)>>>(cl);
    s_tf32     <<<dim3(4, 4, 64), 256, TF_SMEM_S>>>();
    softmax_k  <<<4096, 256>>>();
    transpose_k<<<dim3(16, 16, 64), dim3(32, 8)>>>();
    c_gemm_mma <<<dim3(4, 4, 64), 256, CG_SMEM>>>();
    gate_k     <<<16384, 256>>>(c1w, c1b, c2w, c2b);
    mv_tf32    <<<dim3(1, 8, 32), 256, MV_SMEM>>>();
    proj_tf32  <<<dim3(4, 32, 1), 256, PJ_SMEM>>>(wp, out);
}

// round 16
// speedup vs baseline: 1.0565x; 1.0565x over previous
#include <cuda_runtime.h>
#include <cuda_bf16.h>
#include <math.h>
#include <stdint.h>

// ---------------- problem constants ----------------
#define BB   4
#define NN_  512
#define DD   512
#define HH   8
#define DK   64
#define BH   32            // BB*HH
#define NM   (512*512)     // per-(b,h) matrix elems
#define EPSF 1e-6f

// ---------------- scratch (device globals; no runtime alloc) ----------------
__device__ float g_q0[BH*NN_*DK];
__device__ float g_k0[BH*NN_*DK];
__device__ float g_v0[BH*NN_*DK];
__device__ float g_q1[BH*NN_*DK];
__device__ float g_k1[BH*NN_*DK];
__device__ float g_v1[BH*NN_*DK];
__device__ float g_vT[BH*DK*NN_];    // vT[bh][d][n], d = 0..63

__device__ float g_S0 [BH*NM];       // fp32 (softmax input)
__device__ float g_S1 [BH*NM];
__device__ float g_A0 [BH*NM];       // fp32 (gate leading term)
__device__ float g_M  [BH*NM];

// bf16 gate-feature copies + GEMM operands
__device__ __nv_bfloat16 g_S0b [BH*NM];
__device__ __nv_bfloat16 g_S1b [BH*NM];
__device__ __nv_bfloat16 g_S0Tb[BH*NM];
__device__ __nv_bfloat16 g_S1Tb[BH*NM];
__device__ __nv_bfloat16 g_Cfb [BH*NM];
__device__ __nv_bfloat16 g_Cbb [BH*NM];
__device__ __nv_bfloat16 g_A0b [BH*NM];
__device__ __nv_bfloat16 g_A1b [BH*NM];

__device__ float g_rowsum[BH*NN_];
__device__ float g_attn[BB*NN_*DD];

// ================= small PTX helpers =================
__device__ __forceinline__ uint32_t smem_u32(const void* p) {
    uint32_t a;
    asm("{ .reg .u64 t; cvta.to.shared.u64 t, %1; cvt.u32.u64 %0, t; }" : "=r"(a) : "l"(p));
    return a;
}
__device__ __forceinline__ uint32_t swz128(uint32_t off) { return off ^ ((off >> 3) & 0x70); }

__device__ __forceinline__ void cpasync16(uint32_t dst, const void* src) {
    asm volatile("cp.async.cg.shared.global [%0], [%1], 16;" :: "r"(dst), "l"(src));
}
__device__ __forceinline__ void cp_commit() { asm volatile("cp.async.commit_group;" ::: "memory"); }
template<int N> __device__ __forceinline__ void cp_wait() {
    asm volatile("cp.async.wait_group %0;" :: "n"(N) : "memory");
}
__device__ __forceinline__ void ldmx4(uint32_t& r0, uint32_t& r1, uint32_t& r2, uint32_t& r3,
                                      uint32_t addr) {
    asm volatile("ldmatrix.sync.aligned.m8n8.x4.shared.b16 {%0,%1,%2,%3}, [%4];"
                 : "=r"(r0), "=r"(r1), "=r"(r2), "=r"(r3) : "r"(addr));
}
__device__ __forceinline__ void ldmx4t(uint32_t& r0, uint32_t& r1, uint32_t& r2, uint32_t& r3,
                                       uint32_t addr) {
    asm volatile("ldmatrix.sync.aligned.m8n8.x4.trans.shared.b16 {%0,%1,%2,%3}, [%4];"
                 : "=r"(r0), "=r"(r1), "=r"(r2), "=r"(r3) : "r"(addr));
}
__device__ __forceinline__ void mma16816(float& c0, float& c1, float& c2, float& c3,
                                         uint32_t a0, uint32_t a1, uint32_t a2, uint32_t a3,
                                         uint32_t b0, uint32_t b1) {
    asm volatile("mma.sync.aligned.m16n8k16.row.col.f32.bf16.bf16.f32 "
                 "{%0,%1,%2,%3}, {%4,%5,%6,%7}, {%8,%9}, {%0,%1,%2,%3};"
                 : "+f"(c0), "+f"(c1), "+f"(c2), "+f"(c3)
                 : "r"(a0), "r"(a1), "r"(a2), "r"(a3), "r"(b0), "r"(b1));
}
__device__ __forceinline__ void mma1688tf(float& c0, float& c1, float& c2, float& c3,
                                          uint32_t a0, uint32_t a1, uint32_t a2, uint32_t a3,
                                          uint32_t b0, uint32_t b1) {
    asm volatile("mma.sync.aligned.m16n8k8.row.col.f32.tf32.tf32.f32 "
                 "{%0,%1,%2,%3}, {%4,%5,%6,%7}, {%8,%9}, {%0,%1,%2,%3};"
                 : "+f"(c0), "+f"(c1), "+f"(c2), "+f"(c3)
                 : "r"(a0), "r"(a1), "r"(a2), "r"(a3), "r"(b0), "r"(b1));
}
__device__ __forceinline__ void cvt_tf32(uint32_t& x) {
    asm volatile("cvt.rna.tf32.f32 %0, %0;" : "+r"(x));
}
__device__ __forceinline__ uint32_t pack_bf2(float a, float b) {
    __nv_bfloat162 h = __floats2bfloat162_rn(a, b);
    return *(uint32_t*)&h;
}
__device__ __forceinline__ float2 unpack_bf2(uint32_t u) {
    __nv_bfloat162 h = *(__nv_bfloat162*)&u;
    return make_float2(__bfloat162float(h.x), __bfloat162float(h.y));
}

// fast-math helpers (MUFU-backed approximations)
__device__ __forceinline__ float fast_tanh(float x) {
    float y; asm("tanh.approx.f32 %0, %1;" : "=f"(y) : "f"(x)); return y;
}
__device__ __forceinline__ float fast_ex2(float x) {
    float y; asm("ex2.approx.f32 %0, %1;" : "=f"(y) : "f"(x)); return y;
}
__device__ __forceinline__ float fast_lg2(float x) {
    float y; asm("lg2.approx.f32 %0, %1;" : "=f"(y) : "f"(x)); return y;
}
__device__ __forceinline__ float fast_rcp(float x) {
    float y; asm("rcp.approx.f32 %0, %1;" : "=f"(y) : "f"(x)); return y;
}
#define LOG2E_F 1.4426950408889634f
#define LN2_F   0.6931471805599453f
__device__ __forceinline__ float fast_sigmoid(float x) {
    return fast_rcp(1.f + fast_ex2(-LOG2E_F * x));
}
__device__ __forceinline__ float fast_log(float x) {
    return LN2_F * fast_lg2(x);
}

// ========== mma.sync bf16 NN GEMM for Cf/Cb (trans-B from row-major A, 3-stage) ==========
// C[n][m] = sum_k A[n][k] * B[k][m];  A = A0b/A1b rows (k contiguous),
// B = A1b/A0b itself, [k][m] row-major. B staged as 2 halves of 64 m-cols (128B rows).
#define CG_ST    3
#define CG_KC    64
#define CG_NCH   8
#define CG_STAGE 16384                  // 16KB A + 16KB B per stage half each
#define CG_SMEM  (CG_ST * 2 * CG_STAGE) // 98304

__device__ __forceinline__ void cg_load_chunk(const __nv_bfloat16* Ag, const __nv_bfloat16* Bg,
                                              int m0, int c, uint32_t sA, uint32_t sB, int tid) {
    int k0 = c * CG_KC;
    // A tile: 128 rows (n) x 64 k = 128B per row
#pragma unroll
    for (int f = tid; f < 1024; f += 256) {
        int row = f >> 3, seg = f & 7;
        cpasync16(sA + swz128(row * 128 + seg * 16), Ag + (size_t)row * 512 + k0 + seg * 8);
    }
    // B tile: rows k0..k0+63, cols m0..m0+127, as 2 halves of 64 m-cols (128B rows)
#pragma unroll
    for (int f = tid; f < 1024; f += 256) {
        int h = f >> 9, k = (f >> 3) & 63, seg = f & 7;
        cpasync16(sB + h * 8192 + swz128(k * 128 + seg * 16),
                  Bg + (size_t)(k0 + k) * 512 + m0 + h * 64 + seg * 8);
    }
}

__global__ __launch_bounds__(256, 2) void c_gemm_mma() {
    extern __shared__ char smem_raw[];
    uint32_t sb = smem_u32(smem_raw);
    int tid = threadIdx.x;
    int wid = tid >> 5, lane = tid & 31;
    int wm = wid >> 2, wn = wid & 3;

    int z = blockIdx.z, dir = z >> 5, bh = z & 31;
    const __nv_bfloat16* Ag = (dir ? g_A1b : g_A0b) + (size_t)bh * NM + (size_t)blockIdx.y * 128 * 512;
    const __nv_bfloat16* Bg = (dir ? g_A0b : g_A1b) + (size_t)bh * NM;
    __nv_bfloat16*       Cg = (dir ? g_Cbb : g_Cfb) + (size_t)bh * NM;
    int m0 = blockIdx.x * 128;

#pragma unroll
    for (int c = 0; c < 2; c++) {
        uint32_t st = sb + (uint32_t)c * 2 * CG_STAGE;
        cg_load_chunk(Ag, Bg, m0, c, st, st + CG_STAGE, tid);
        cp_commit();
    }

    float acc[4][4][4];
#pragma unroll
    for (int i = 0; i < 4; i++)
#pragma unroll
        for (int j = 0; j < 4; j++)
#pragma unroll
            for (int k = 0; k < 4; k++) acc[i][j][k] = 0.f;

    // A-fragment lane geometry (non-trans, rows = n)
    int rowA  = wm * 64 + (lane & 15);
    int hiA   = lane >> 4;
    int sxA   = rowA & 7;
    // B-fragment lane geometry (trans ldmatrix from [k][m] rows)
    int krB   = lane & 15;                // + ks*16
    int ngrpB = lane >> 4;                // 0/1 -> +8 m

    for (int c = 0; c < CG_NCH; c++) {
        if (c + 2 < CG_NCH) {
            uint32_t st = sb + (uint32_t)((c + 2) % CG_ST) * 2 * CG_STAGE;
            cg_load_chunk(Ag, Bg, m0, c + 2, st, st + CG_STAGE, tid);
            cp_commit();
            cp_wait<2>();
        } else if (c + 1 < CG_NCH) {
            cp_wait<1>();
        } else {
            cp_wait<0>();
        }
        __syncthreads();
        uint32_t sA  = sb + (uint32_t)(c % CG_ST) * 2 * CG_STAGE;
        uint32_t sBm = sA + CG_STAGE;
#pragma unroll
        for (int ks = 0; ks < 4; ks++) {
            uint32_t a[4][4];
#pragma unroll
            for (int mf = 0; mf < 4; mf++) {
                uint32_t addr = sA + rowA * 128 + mf * 2048 + 16 * ((2 * ks + hiA) ^ sxA);
                ldmx4(a[mf][0], a[mf][1], a[mf][2], a[mf][3], addr);
            }
#pragma unroll
            for (int nf = 0; nf < 2; nf++) {
                int nseg = wn * 32 + nf * 16 + ngrpB * 8;   // absolute m-col in tile
                int half = nseg >> 6, lc = nseg & 63;
                int kr = ks * 16 + krB;
                uint32_t addr = sBm + half * 8192 + swz128(kr * 128 + lc * 2);
                uint32_t b0, b1, b2, b3;
                ldmx4t(b0, b1, b2, b3, addr);
#pragma unroll
                for (int mf = 0; mf < 4; mf++) {
                    mma16816(acc[mf][2*nf  ][0], acc[mf][2*nf  ][1], acc[mf][2*nf  ][2], acc[mf][2*nf  ][3],
                             a[mf][0], a[mf][1], a[mf][2], a[mf][3], b0, b1);
                    mma16816(acc[mf][2*nf+1][0], acc[mf][2*nf+1][1], acc[mf][2*nf+1][2], acc[mf][2*nf+1][3],
                             a[mf][0], a[mf][1], a[mf][2], a[mf][3], b2, b3);
                }
            }
        }
        __syncthreads();
    }

    int r0 = blockIdx.y * 128;
#pragma unroll
    for (int mf = 0; mf < 4; mf++) {
        int r = r0 + wm * 64 + mf * 16 + (lane >> 2);
#pragma unroll
        for (int nfr = 0; nfr < 4; nfr++) {
            int col = m0 + wn * 32 + nfr * 8 + 2 * (lane & 3);
            *(uint32_t*)&Cg[(size_t)r * 512 + col]       = pack_bf2(acc[mf][nfr][0], acc[mf][nfr][1]);
            *(uint32_t*)&Cg[(size_t)(r + 8) * 512 + col] = pack_bf2(acc[mf][nfr][2], acc[mf][nfr][3]);
        }
    }
}

// ================= tf32 mma.sync NT GEMM core (128x128, 3-stage) =================
#define TF_STAGE 16384
#define TF_SMEM  (3 * 2 * TF_STAGE)      // 98304 (qkv)
#define TF_SMEM_S (2 * 2 * TF_STAGE)     // 65536 (s_tf32, K=64)

__device__ __forceinline__ void tf_load_chunk(const float* Ag, const float* Bg,
                                              int lda, int ldb, int c,
                                              uint32_t sA, uint32_t sB, int tid) {
    int k0 = c * 32;
#pragma unroll
    for (int f = tid; f < 1024; f += 256) {
        int row = f >> 3, seg = f & 7;
        cpasync16(sA + swz128(row * 128 + seg * 16), Ag + (size_t)row * lda + k0 + seg * 4);
    }
#pragma unroll
    for (int f = tid; f < 1024; f += 256) {
        int row = f >> 3, seg = f & 7;
        cpasync16(sB + swz128(row * 128 + seg * 16), Bg + (size_t)row * ldb + k0 + seg * 4);
    }
}

__device__ __forceinline__ void tf32_core(const float* Ag, const float* Bg,
                                          int lda, int ldb, int nch,
                                          uint32_t sb, int tid, float acc[4][4][4]) {
    int lane = tid & 31, wid = tid >> 5;
    int wm = wid >> 2, wn = wid & 3;

    int npro = nch < 2 ? nch : 2;
    for (int c = 0; c < npro; c++) {
        uint32_t st = sb + (uint32_t)c * 2 * TF_STAGE;
        tf_load_chunk(Ag, Bg, lda, ldb, c, st, st + TF_STAGE, tid);
        cp_commit();
    }

    int rA_off = wm * 64 + (lane & 7) + ((lane >> 3) & 1) * 8;
    int csA    = lane >> 4;
    int rB_off = wn * 32 + (lane & 7) + (lane >> 4) * 8;
    int ksB    = (lane >> 3) & 1;

    for (int c = 0; c < nch; c++) {
        if (c + 2 < nch) {
            uint32_t st = sb + (uint32_t)((c + 2) % 3) * 2 * TF_STAGE;
            tf_load_chunk(Ag, Bg, lda, ldb, c + 2, st, st + TF_STAGE, tid);
            cp_commit();
            cp_wait<2>();
        } else if (c + 1 < nch) {
            cp_wait<1>();
        } else {
            cp_wait<0>();
        }
        __syncthreads();
        uint32_t sA = sb + (uint32_t)(c % 3) * 2 * TF_STAGE;
        uint32_t sB = sA + TF_STAGE;
#pragma unroll
        for (int ks = 0; ks < 4; ks++) {
            uint32_t a[4][4];
#pragma unroll
            for (int mf = 0; mf < 4; mf++) {
                int row = rA_off + mf * 16;
                uint32_t addr = sA + row * 128 + 16 * ((2 * ks + csA) ^ (row & 7));
                ldmx4(a[mf][0], a[mf][1], a[mf][2], a[mf][3], addr);
                cvt_tf32(a[mf][0]); cvt_tf32(a[mf][1]); cvt_tf32(a[mf][2]); cvt_tf32(a[mf][3]);
            }
            uint32_t b[2][4];
#pragma unroll
            for (int p = 0; p < 2; p++) {
                int row = rB_off + p * 16;
                uint32_t addr = sB + row * 128 + 16 * ((2 * ks + ksB) ^ (row & 7));
                ldmx4(b[p][0], b[p][1], b[p][2], b[p][3], addr);
                cvt_tf32(b[p][0]); cvt_tf32(b[p][1]); cvt_tf32(b[p][2]); cvt_tf32(b[p][3]);
            }
#pragma unroll
            for (int mf = 0; mf < 4; mf++)
#pragma unroll
                for (int p = 0; p < 2; p++) {
                    mma1688tf(acc[mf][2*p  ][0], acc[mf][2*p  ][1], acc[mf][2*p  ][2], acc[mf][2*p  ][3],
                              a[mf][0], a[mf][1], a[mf][2], a[mf][3], b[p][0], b[p][1]);
                    mma1688tf(acc[mf][2*p+1][0], acc[mf][2*p+1][1], acc[mf][2*p+1][2], acc[mf][2*p+1][3],
                              a[mf][0], a[mf][1], a[mf][2], a[mf][3], b[p][2], b[p][3]);
                }
        }
        __syncthreads();
    }
}

// ---------------- 1) QKV GEMM (tf32, 128x128 tiles — R13 proven config) ----------------
__global__ __launch_bounds__(256, 2) void qkv_tf32(const float* __restrict__ x,
                                                   const float* __restrict__ w0,
                                                   const float* __restrict__ w1) {
    extern __shared__ char smem_raw[];
    uint32_t sb = smem_u32(smem_raw);
    int tid = threadIdx.x, lane = tid & 31, wid = tid >> 5;
    int wm = wid >> 2, wn = wid & 3;
    int set = blockIdx.z;
    const float* W = set ? w1 : w0;
    int m0 = blockIdx.y * 128, n0 = blockIdx.x * 128;

    float acc[4][4][4];
#pragma unroll
    for (int i = 0; i < 4; i++)
#pragma unroll
        for (int j = 0; j < 4; j++)
#pragma unroll
            for (int k = 0; k < 4; k++) acc[i][j][k] = 0.f;

    tf32_core(x + (size_t)m0 * 512, W + (size_t)n0 * 512, 512, 512, 16, sb, tid, acc);

    float* q = set ? g_q1 : g_q0;
    float* kk = set ? g_k1 : g_k0;
    float* v = set ? g_v1 : g_v0;
#pragma unroll
    for (int mf = 0; mf < 4; mf++) {
        int r = m0 + wm * 64 + mf * 16 + (lane >> 2);
#pragma unroll
        for (int half = 0; half < 2; half++) {
            int rr = r + half * 8;
            int b = rr >> 9, n = rr & 511;
#pragma unroll
            for (int nf = 0; nf < 4; nf++) {
                int col = n0 + wn * 32 + nf * 8 + 2 * (lane & 3);
                int t = col >> 9, rem = col & 511, h = rem >> 6, d = rem & 63;
                float* dst = (t == 0) ? q : (t == 1) ? kk : v;
                float2 val = half ? make_float2(acc[mf][nf][2], acc[mf][nf][3])
                                  : make_float2(acc[mf][nf][0], acc[mf][nf][1]);
                *(float2*)&dst[(((size_t)b*8 + h)*512 + n)*64 + d] = val;
            }
        }
    }
}

// ---------------- 3) S = scale * q @ k^T; writes S fp32, S bf16, S^T bf16 ----------
__global__ __launch_bounds__(256, 2) void s_tf32() {
    extern __shared__ char smem_raw[];
    uint32_t sb = smem_u32(smem_raw);
    int tid = threadIdx.x, lane = tid & 31, wid = tid >> 5;
    int wm = wid >> 2, wn = wid & 3;
    int z = blockIdx.z, pair = z >> 5, bh = z & 31;
    const float* Q = (pair ? g_q1 : g_q0) + (size_t)bh * NN_ * DK;
    const float* K = (pair ? g_k1 : g_k0) + (size_t)bh * NN_ * DK;
    float* C  = (pair ? g_S1  : g_S0 ) + (size_t)bh * NM;
    __nv_bfloat16* Cb  = (pair ? g_S1b  : g_S0b ) + (size_t)bh * NM;
    __nv_bfloat16* CTb = (pair ? g_S1Tb : g_S0Tb) + (size_t)bh * NM;
    int m0 = blockIdx.y * 128, n0 = blockIdx.x * 128;

    float acc[4][4][4];
#pragma unroll
    for (int i = 0; i < 4; i++)
#pragma unroll
        for (int j = 0; j < 4; j++)
#pragma unroll
            for (int k = 0; k < 4; k++) acc[i][j][k] = 0.f;

    tf32_core(Q + (size_t)m0 * 64, K + (size_t)n0 * 64, 64, 64, 2, sb, tid, acc);

#pragma unroll
    for (int mf = 0; mf < 4; mf++) {
        int r = m0 + wm * 64 + mf * 16 + (lane >> 2);
#pragma unroll
        for (int nf = 0; nf < 4; nf++) {
            int col = n0 + wn * 32 + nf * 8 + 2 * (lane & 3);
            float v0 = 0.125f * acc[mf][nf][0], v1 = 0.125f * acc[mf][nf][1];
            float v2 = 0.125f * acc[mf][nf][2], v3 = 0.125f * acc[mf][nf][3];
            *(float2*)&C[(size_t)r * 512 + col]        = make_float2(v0, v1);
            *(float2*)&C[(size_t)(r + 8) * 512 + col]  = make_float2(v2, v3);
            *(uint32_t*)&Cb[(size_t)r * 512 + col]       = pack_bf2(v0, v1);
            *(uint32_t*)&Cb[(size_t)(r + 8) * 512 + col] = pack_bf2(v2, v3);
        }
    }

    float* tile = (float*)smem_raw;
#pragma unroll
    for (int hp = 0; hp < 2; hp++) {
        __syncthreads();
#pragma unroll
        for (int mf = 0; mf < 4; mf++) {
            int r = wm * 64 + mf * 16 + (lane >> 2);
#pragma unroll
            for (int nf = 0; nf < 4; nf++) {
                int cbase = wn * 32 + nf * 8 + 2 * (lane & 3);
                if ((cbase >> 6) == hp) {
                    int lc = cbase & 63;
                    tile[(lc    ) * 132 + r    ] = 0.125f * acc[mf][nf][0];
                    tile[(lc + 1) * 132 + r    ] = 0.125f * acc[mf][nf][1];
                    tile[(lc    ) * 132 + r + 8] = 0.125f * acc[mf][nf][2];
                    tile[(lc + 1) * 132 + r + 8] = 0.125f * acc[mf][nf][3];
                }
            }
        }
        __syncthreads();
#pragma unroll
        for (int f = tid; f < 2048; f += 256) {
            int c = f >> 5, seg = f & 31;
            float4 val = *(float4*)&tile[c * 132 + seg * 4];
            uint2 pk;
            pk.x = pack_bf2(val.x, val.y);
            pk.y = pack_bf2(val.z, val.w);
            *(uint2*)&CTb[(size_t)(n0 + hp * 64 + c) * 512 + m0 + seg * 4] = pk;
        }
    }
}

// ================= 64x128-tile tf32 core (proj) =================
#define PJ_ST_A  8192
#define PJ_ST_B  16384
#define PJ_STAGE (PJ_ST_A + PJ_ST_B)     // 24576
#define PJ_SMEM  (3 * PJ_STAGE)          // 73728

__device__ __forceinline__ void pj_load_chunk(const float* Ag, const float* Bg, int c,
                                              uint32_t sA, uint32_t sB, int tid) {
    int k0 = c * 32;
#pragma unroll
    for (int f = tid; f < 512; f += 256) {
        int row = f >> 3, seg = f & 7;
        cpasync16(sA + swz128(row * 128 + seg * 16), Ag + (size_t)row * 512 + k0 + seg * 4);
    }
#pragma unroll
    for (int f = tid; f < 1024; f += 256) {
        int row = f >> 3, seg = f & 7;
        cpasync16(sB + swz128(row * 128 + seg * 16), Bg + (size_t)row * 512 + k0 + seg * 4);
    }
}

__device__ __forceinline__ void pj_core(const float* Ag, const float* Bg,
                                        uint32_t sb, int tid, float acc[2][4][4]) {
    int lane = tid & 31, wid = tid >> 5;
    int wm = wid >> 2, wn = wid & 3;

#pragma unroll
    for (int c = 0; c < 2; c++) {
        uint32_t st = sb + (uint32_t)c * PJ_STAGE;
        pj_load_chunk(Ag, Bg, c, st, st + PJ_ST_A, tid);
        cp_commit();
    }

    int rA_off = wm * 32 + (lane & 7) + ((lane >> 3) & 1) * 8;
    int csA    = lane >> 4;
    int rB_off = wn * 32 + (lane & 7) + (lane >> 4) * 8;
    int ksB    = (lane >> 3) & 1;

    for (int c = 0; c < 16; c++) {
        if (c + 2 < 16) {
            uint32_t st = sb + (uint32_t)((c + 2) % 3) * PJ_STAGE;
            pj_load_chunk(Ag, Bg, c + 2, st, st + PJ_ST_A, tid);
            cp_commit();
            cp_wait<2>();
        } else if (c + 1 < 16) {
            cp_wait<1>();
        } else {
            cp_wait<0>();
        }
        __syncthreads();
        uint32_t sA = sb + (uint32_t)(c % 3) * PJ_STAGE;
        uint32_t sB = sA + PJ_ST_A;
#pragma unroll
        for (int ks = 0; ks < 4; ks++) {
            uint32_t a[2][4];
#pragma unroll
            for (int mf = 0; mf < 2; mf++) {
                int row = rA_off + mf * 16;
                uint32_t addr = sA + row * 128 + 16 * ((2 * ks + csA) ^ (row & 7));
                ldmx4(a[mf][0], a[mf][1], a[mf][2], a[mf][3], addr);
                cvt_tf32(a[mf][0]); cvt_tf32(a[mf][1]); cvt_tf32(a[mf][2]); cvt_tf32(a[mf][3]);
            }
            uint32_t b[2][4];
#pragma unroll
            for (int p = 0; p < 2; p++) {
                int row = rB_off + p * 16;
                uint32_t addr = sB + row * 128 + 16 * ((2 * ks + ksB) ^ (row & 7));
                ldmx4(b[p][0], b[p][1], b[p][2], b[p][3], addr);
                cvt_tf32(b[p][0]); cvt_tf32(b[p][1]); cvt_tf32(b[p][2]); cvt_tf32(b[p][3]);
            }
#pragma unroll
            for (int mf = 0; mf < 2; mf++)
#pragma unroll
                for (int p = 0; p < 2; p++) {
                    mma1688tf(acc[mf][2*p  ][0], acc[mf][2*p  ][1], acc[mf][2*p  ][2], acc[mf][2*p  ][3],
                              a[mf][0], a[mf][1], a[mf][2], a[mf][3], b[p][0], b[p][1]);
                    mma1688tf(acc[mf][2*p+1][0], acc[mf][2*p+1][1], acc[mf][2*p+1][2], acc[mf][2*p+1][3],
                              a[mf][0], a[mf][1], a[mf][2], a[mf][3], b[p][2], b[p][3]);
                }
        }
        __syncthreads();
    }
}

// ---------------- 9) final projection (64x128 tiles) ----------------
__global__ __launch_bounds__(256, 2) void proj_tf32(const float* __restrict__ wp,
                                                    float* __restrict__ out) {
    extern __shared__ char smem_raw[];
    uint32_t sb = smem_u32(smem_raw);
    int tid = threadIdx.x, lane = tid & 31, wid = tid >> 5;
    int wm = wid >> 2, wn = wid & 3;
    int m0 = blockIdx.y * 64, n0 = blockIdx.x * 128;

    float acc[2][4][4];
#pragma unroll
    for (int i = 0; i < 2; i++)
#pragma unroll
        for (int j = 0; j < 4; j++)
#pragma unroll
            for (int k = 0; k < 4; k++) acc[i][j][k] = 0.f;

    pj_core(g_attn + (size_t)m0 * 512, wp + (size_t)n0 * 512, sb, tid, acc);

#pragma unroll
    for (int mf = 0; mf < 2; mf++) {
        int r = m0 + wm * 32 + mf * 16 + (lane >> 2);
#pragma unroll
        for (int nf = 0; nf < 4; nf++) {
            int col = n0 + wn * 32 + nf * 8 + 2 * (lane & 3);
            *(float2*)&out[(size_t)r * 512 + col]       = make_float2(acc[mf][nf][0], acc[mf][nf][1]);
            *(float2*)&out[(size_t)(r + 8) * 512 + col] = make_float2(acc[mf][nf][2], acc[mf][nf][3]);
        }
    }
}

// ================= 8) mv — 64x64 tiles (256 CTAs) =================
#define MV_ST_A  8192
#define MV_ST_B  8192
#define MV_STAGE (MV_ST_A + MV_ST_B)     // 16384
#define MV_SMEM  (3 * MV_STAGE)          // 49152

__device__ __forceinline__ void mv_load_chunk(const float* Ag, const float* Bg, int c,
                                              uint32_t sA, uint32_t sB, int tid) {
    int k0 = c * 32;
#pragma unroll
    for (int f = tid; f < 512; f += 256) {
        int row = f >> 3, seg = f & 7;
        cpasync16(sA + swz128(row * 128 + seg * 16), Ag + (size_t)row * 512 + k0 + seg * 4);
    }
#pragma unroll
    for (int f = tid; f < 512; f += 256) {
        int row = f >> 3, seg = f & 7;
        cpasync16(sB + swz128(row * 128 + seg * 16), Bg + (size_t)row * 512 + k0 + seg * 4);
    }
}

__global__ __launch_bounds__(256, 2) void mv_tf32() {
    extern __shared__ char smem_raw[];
    uint32_t sb = smem_u32(smem_raw);
    int tid = threadIdx.x, lane = tid & 31, wid = tid >> 5;
    int wm = wid >> 2, wn = wid & 3;
    int z = blockIdx.z;
    int m0 = blockIdx.y * 64;

    const float* Ag = g_M  + (size_t)z * NM + (size_t)m0 * 512;
    const float* Bg = g_vT + (size_t)z * DK * 512;

    float acc[2][2][4];
#pragma unroll
    for (int i = 0; i < 2; i++)
#pragma unroll
        for (int j = 0; j < 2; j++)
#pragma unroll
            for (int k = 0; k < 4; k++) acc[i][j][k] = 0.f;

#pragma unroll
    for (int c = 0; c < 2; c++) {
        uint32_t st = sb + (uint32_t)c * MV_STAGE;
        mv_load_chunk(Ag, Bg, c, st, st + MV_ST_A, tid);
        cp_commit();
    }

    int rA_off = wm * 32 + (lane & 7) + ((lane >> 3) & 1) * 8;
    int csA    = lane >> 4;
    int rB_off = wn * 16 + (lane & 7) + (lane >> 4) * 8;
    int ksB    = (lane >> 3) & 1;

    for (int c = 0; c < 16; c++) {
        if (c + 2 < 16) {
            uint32_t st = sb + (uint32_t)((c + 2) % 3) * MV_STAGE;
            mv_load_chunk(Ag, Bg, c + 2, st, st + MV_ST_A, tid);
            cp_commit();
            cp_wait<2>();
        } else if (c + 1 < 16) {
            cp_wait<1>();
        } else {
            cp_wait<0>();
        }
        __syncthreads();
        uint32_t sA = sb + (uint32_t)(c % 3) * MV_STAGE;
        uint32_t sB = sA + MV_ST_A;
#pragma unroll
        for (int ks = 0; ks < 4; ks++) {
            uint32_t a[2][4];
#pragma unroll
            for (int mf = 0; mf < 2; mf++) {
                int row = rA_off + mf * 16;
                uint32_t addr = sA + row * 128 + 16 * ((2 * ks + csA) ^ (row & 7));
                ldmx4(a[mf][0], a[mf][1], a[mf][2], a[mf][3], addr);
                cvt_tf32(a[mf][0]); cvt_tf32(a[mf][1]); cvt_tf32(a[mf][2]); cvt_tf32(a[mf][3]);
            }
            uint32_t b0, b1, b2, b3;
            {
                int row = rB_off;
                uint32_t addr = sB + row * 128 + 16 * ((2 * ks + ksB) ^ (row & 7));
                ldmx4(b0, b1, b2, b3, addr);
                cvt_tf32(b0); cvt_tf32(b1); cvt_tf32(b2); cvt_tf32(b3);
            }
#pragma unroll
            for (int mf = 0; mf < 2; mf++) {
                mma1688tf(acc[mf][0][0], acc[mf][0][1], acc[mf][0][2], acc[mf][0][3],
                          a[mf][0], a[mf][1], a[mf][2], a[mf][3], b0, b1);
                mma1688tf(acc[mf][1][0], acc[mf][1][1], acc[mf][1][2], acc[mf][1][3],
                          a[mf][0], a[mf][1], a[mf][2], a[mf][3], b2, b3);
            }
        }
        __syncthreads();
    }

    int b = z >> 3, h = z & 7;
#pragma unroll
    for (int mf = 0; mf < 2; mf++) {
        int n = m0 + wm * 32 + mf * 16 + (lane >> 2);
        float sc0 = 1.f / (g_rowsum[z * 512 + n] + EPSF);
        float sc1 = 1.f / (g_rowsum[z * 512 + n + 8] + EPSF);
#pragma unroll
        for (int nf = 0; nf < 2; nf++) {
            int d = wn * 16 + nf * 8 + 2 * (lane & 3);
            *(float2*)&g_attn[((size_t)b * 512 + n) * 512 + h * 64 + d] =
                make_float2(acc[mf][nf][0] * sc0, acc[mf][nf][1] * sc0);
            *(float2*)&g_attn[((size_t)b * 512 + n + 8) * 512 + h * 64 + d] =
                make_float2(acc[mf][nf][2] * sc1, acc[mf][nf][3] * sc1);
        }
    }
}

// ---------------- 2) v mix + transpose: vT[bh][d][n], d = 0..63 ----------------
__global__ void vmix_k(const float* __restrict__ cl) {
    __shared__ float t[32][33];
    float a = fast_sigmoid(cl[0]);
    int bh = blockIdx.z;
    int d0 = blockIdx.x * 32, n0 = blockIdx.y * 32;
    const float* v0 = g_v0 + (size_t)bh * NN_ * DK;
    const float* v1 = g_v1 + (size_t)bh * NN_ * DK;
    float* vt = g_vT + (size_t)bh * DK * 512;
    int tx = threadIdx.x, ty = threadIdx.y;
#pragma unroll
    for (int i = 0; i < 32; i += 8) {
        size_t idx = (size_t)(n0 + ty + i) * 64 + d0 + tx;
        t[ty + i][tx] = (1.f - a) * v0[idx] + a * v1[idx];
    }
    __syncthreads();
#pragma unroll
    for (int i = 0; i < 32; i += 8)
        vt[(size_t)(d0 + ty + i) * 512 + n0 + tx] = t[tx][ty + i];
}

// ---------------- 4) warp-per-row softmax (A0 fp32+bf16; A1 bf16 only) ----------------
__global__ void softmax_k() {
    int gw = blockIdx.x * 8 + (threadIdx.x >> 5);
    int pair = gw >> 14, r = gw & 16383;
    const float* src = (pair ? g_S1 : g_S0) + (size_t)r * 512;
    __nv_bfloat16* dstb = (pair ? g_A1b : g_A0b) + (size_t)r * 512;
    int lane = threadIdx.x & 31;

    float4 v[4];
#pragma unroll
    for (int q = 0; q < 4; q++) v[q] = ((const float4*)src)[q * 32 + lane];

    float mx = -1e30f;
#pragma unroll
    for (int q = 0; q < 4; q++)
        mx = fmaxf(mx, fmaxf(fmaxf(v[q].x, v[q].y), fmaxf(v[q].z, v[q].w)));
#pragma unroll
    for (int s = 16; s > 0; s >>= 1) mx = fmaxf(mx, __shfl_xor_sync(0xffffffffu, mx, s));

    float sum = 0.f;
#pragma unroll
    for (int q = 0; q < 4; q++) {
        v[q].x = expf(v[q].x - mx);  v[q].y = expf(v[q].y - mx);
        v[q].z = expf(v[q].z - mx);  v[q].w = expf(v[q].w - mx);
        sum += v[q].x + v[q].y + v[q].z + v[q].w;
    }
#pragma unroll
    for (int s = 16; s > 0; s >>= 1) sum += __shfl_xor_sync(0xffffffffu, sum, s);
    float inv = 1.f / sum;

    float* dst0 = g_A0 + (size_t)r * 512;
#pragma unroll
    for (int q = 0; q < 4; q++) {
        float4 o = make_float4(v[q].x * inv, v[q].y * inv, v[q].z * inv, v[q].w * inv);
        if (pair == 0) ((float4*)dst0)[q * 32 + lane] = o;
        uint2 pk;
        pk.x = pack_bf2(o.x, o.y);
        pk.y = pack_bf2(o.z, o.w);
        ((uint2*)dstb)[q * 32 + lane] = pk;
    }
}

// ---------------- 7) gate + combine (vectorized: 2 elems/thread, 1 pass) ----------
__global__ void gate_k(const float* __restrict__ c1w, const float* __restrict__ c1b,
                       const float* __restrict__ c2w, const float* __restrict__ c2b) {
    int row = blockIdx.x;
    size_t base = (size_t)row * 512;
    __shared__ float sw1[96], sb1[16], sw2[64], sb2[4];
    int tid = threadIdx.x;
    if (tid < 96)       sw1[tid]       = c1w[tid];
    else if (tid < 112) sb1[tid - 96]  = c1b[tid - 96];
    else if (tid < 176) sw2[tid - 112] = c2w[tid - 112];
    else if (tid < 180) sb2[tid - 176] = c2b[tid - 176];
    __syncthreads();

    int m = tid * 2;
    float2 f0v = unpack_bf2(*(const uint32_t*)&g_S0b [base + m]);
    float2 f1v = unpack_bf2(*(const uint32_t*)&g_S1b [base + m]);
    float2 f2v = unpack_bf2(*(const uint32_t*)&g_S0Tb[base + m]);
    float2 f3v = unpack_bf2(*(const uint32_t*)&g_S1Tb[base + m]);
    float2 cfv = unpack_bf2(*(const uint32_t*)&g_Cfb [base + m]);
    float2 cbv = unpack_bf2(*(const uint32_t*)&g_Cbb [base + m]);
    float2 a0v = *(const float2*)&g_A0[base + m];
    float2 a1v = unpack_bf2(*(const uint32_t*)&g_A1b[base + m]);

    float f0a[2] = { f0v.x, f0v.y }, f1a[2] = { f1v.x, f1v.y };
    float f2a[2] = { f2v.x, f2v.y }, f3a[2] = { f3v.x, f3v.y };
    float cfa[2] = { cfv.x, cfv.y }, cba[2] = { cbv.x, cbv.y };
    float a0a[2] = { a0v.x, a0v.y }, a1a[2] = { a1v.x, a1v.y };
    float mv[2];
    float lsum = 0.f;
#pragma unroll
    for (int e = 0; e < 2; e++) {
        float f4 = fast_log(cfa[e] + EPSF);
        float f5 = fast_log(cba[e] + EPSF);
        float a2[4] = { sb2[0], sb2[1], sb2[2], sb2[3] };
#pragma unroll
        for (int o = 0; o < 16; o++) {
            float h = sb1[o] + sw1[o*6+0]*f0a[e] + sw1[o*6+1]*f1a[e] + sw1[o*6+2]*f2a[e]
                             + sw1[o*6+3]*f3a[e] + sw1[o*6+4]*f4     + sw1[o*6+5]*f5;
            float u = 0.7978845608028654f * (h + 0.044715f * h * h * h);
            float g = 0.5f * h * (1.f + fast_tanh(u));
            a2[0] += sw2[ 0 + o] * g;
            a2[1] += sw2[16 + o] * g;
            a2[2] += sw2[32 + o] * g;
            a2[3] += sw2[48 + o] * g;
        }
        float G0 = fast_sigmoid(a2[0]);
        float G1 = fast_sigmoid(a2[1]);
        float G2 = fast_sigmoid(a2[2]);
        float G3 = fast_sigmoid(a2[3]);
        float aand = a0a[e] * a1a[e];
        float aor  = a0a[e] + a1a[e] - aand;
        float anot = a0a[e] * (1.f - 0.5f * a1a[e]);
        mv[e] = a0a[e] + G0*aand + G1*aor + G2*anot + G3*cfa[e];
        lsum += mv[e];
    }
    *(float2*)&g_M[base + m] = make_float2(mv[0], mv[1]);

    __shared__ float red[256];
    red[tid] = lsum;
    __syncthreads();
    for (int s = 128; s > 0; s >>= 1) { if (tid < s) red[tid] += red[tid+s]; __syncthreads(); }
    if (tid == 0) g_rowsum[row] = red[0];
}

// ---------------- launch ----------------
extern "C" void kernel_launch(void* const* d_in, const int* in_sizes, int n_in,
                              void* d_out, int out_size) {
    const float* x    = (const float*)d_in[0];
    const float* w0   = (const float*)d_in[1];
    const float* w1   = (const float*)d_in[2];
    const float* c1w  = (const float*)d_in[3];
    const float* c1b  = (const float*)d_in[4];
    const float* c2w  = (const float*)d_in[5];
    const float* c2b  = (const float*)d_in[6];
    const float* wp   = (const float*)d_in[7];
    const float* cl   = (const float*)d_in[8];
    float* out = (float*)d_out;

    cudaFuncSetAttribute(c_gemm_mma, cudaFuncAttributeMaxDynamicSharedMemorySize, CG_SMEM);
    cudaFuncSetAttribute(qkv_tf32,   cudaFuncAttributeMaxDynamicSharedMemorySize, TF_SMEM);
    cudaFuncSetAttribute(s_tf32,     cudaFuncAttributeMaxDynamicSharedMemorySize, TF_SMEM_S);
    cudaFuncSetAttribute(mv_tf32,    cudaFuncAttributeMaxDynamicSharedMemorySize, MV_SMEM);
    cudaFuncSetAttribute(proj_tf32,  cudaFuncAttributeMaxDynamicSharedMemorySize, PJ_SMEM);

    qkv_tf32   <<<dim3(12, 16, 2), 256, TF_SMEM>>>(x, w0, w1);
    vmix_k     <<<dim3(2, 16, 32), dim3(32, 8)>>>(cl);
    s_tf32     <<<dim3(4, 4, 64), 256, TF_SMEM_S>>>();
    softmax_k  <<<4096, 256>>>();
    c_gemm_mma <<<dim3(4, 4, 64), 256, CG_SMEM>>>();
    gate_k     <<<16384, 256>>>(c1w, c1b, c2w, c2b);
    mv_tf32    <<<dim3(1, 8, 32), 256, MV_SMEM>>>();
    proj_tf32  <<<dim3(4, 32, 1), 256, PJ_SMEM>>>(wp, out);
}

// round 17
// speedup vs baseline: 1.0641x; 1.0072x over previous
#include <cuda_runtime.h>
#include <cuda_bf16.h>
#include <math.h>
#include <stdint.h>

// ---------------- problem constants ----------------
#define BB   4
#define NN_  512
#define DD   512
#define HH   8
#define DK   64
#define BH   32            // BB*HH
#define NM   (512*512)     // per-(b,h) matrix elems
#define EPSF 1e-6f

// ---------------- scratch (device globals; no runtime alloc) ----------------
__device__ float g_q0[BH*NN_*DK];
__device__ float g_k0[BH*NN_*DK];
__device__ float g_v0[BH*NN_*DK];
__device__ float g_q1[BH*NN_*DK];
__device__ float g_k1[BH*NN_*DK];
__device__ float g_v1[BH*NN_*DK];
__device__ float g_vT[BH*DK*NN_];    // vT[bh][d][n], d = 0..63

__device__ float g_A0 [BH*NM];       // fp32 (gate leading term)
__device__ float g_M  [BH*NM];

// bf16 gate-feature copies + GEMM operands
__device__ __nv_bfloat16 g_S0b [BH*NM];
__device__ __nv_bfloat16 g_S1b [BH*NM];
__device__ __nv_bfloat16 g_S0Tb[BH*NM];
__device__ __nv_bfloat16 g_S1Tb[BH*NM];
__device__ __nv_bfloat16 g_Cfb [BH*NM];
__device__ __nv_bfloat16 g_Cbb [BH*NM];
__device__ __nv_bfloat16 g_A0b [BH*NM];
__device__ __nv_bfloat16 g_A1b [BH*NM];

__device__ float g_rowsum[BH*NN_];
__device__ float g_attn[BB*NN_*DD];

// ================= small PTX helpers =================
__device__ __forceinline__ uint32_t smem_u32(const void* p) {
    uint32_t a;
    asm("{ .reg .u64 t; cvta.to.shared.u64 t, %1; cvt.u32.u64 %0, t; }" : "=r"(a) : "l"(p));
    return a;
}
__device__ __forceinline__ uint32_t swz128(uint32_t off) { return off ^ ((off >> 3) & 0x70); }

__device__ __forceinline__ void cpasync16(uint32_t dst, const void* src) {
    asm volatile("cp.async.cg.shared.global [%0], [%1], 16;" :: "r"(dst), "l"(src));
}
__device__ __forceinline__ void cp_commit() { asm volatile("cp.async.commit_group;" ::: "memory"); }
template<int N> __device__ __forceinline__ void cp_wait() {
    asm volatile("cp.async.wait_group %0;" :: "n"(N) : "memory");
}
__device__ __forceinline__ void ldmx4(uint32_t& r0, uint32_t& r1, uint32_t& r2, uint32_t& r3,
                                      uint32_t addr) {
    asm volatile("ldmatrix.sync.aligned.m8n8.x4.shared.b16 {%0,%1,%2,%3}, [%4];"
                 : "=r"(r0), "=r"(r1), "=r"(r2), "=r"(r3) : "r"(addr));
}
__device__ __forceinline__ void ldmx4t(uint32_t& r0, uint32_t& r1, uint32_t& r2, uint32_t& r3,
                                       uint32_t addr) {
    asm volatile("ldmatrix.sync.aligned.m8n8.x4.trans.shared.b16 {%0,%1,%2,%3}, [%4];"
                 : "=r"(r0), "=r"(r1), "=r"(r2), "=r"(r3) : "r"(addr));
}
__device__ __forceinline__ void mma16816(float& c0, float& c1, float& c2, float& c3,
                                         uint32_t a0, uint32_t a1, uint32_t a2, uint32_t a3,
                                         uint32_t b0, uint32_t b1) {
    asm volatile("mma.sync.aligned.m16n8k16.row.col.f32.bf16.bf16.f32 "
                 "{%0,%1,%2,%3}, {%4,%5,%6,%7}, {%8,%9}, {%0,%1,%2,%3};"
                 : "+f"(c0), "+f"(c1), "+f"(c2), "+f"(c3)
                 : "r"(a0), "r"(a1), "r"(a2), "r"(a3), "r"(b0), "r"(b1));
}
__device__ __forceinline__ void mma1688tf(float& c0, float& c1, float& c2, float& c3,
                                          uint32_t a0, uint32_t a1, uint32_t a2, uint32_t a3,
                                          uint32_t b0, uint32_t b1) {
    asm volatile("mma.sync.aligned.m16n8k8.row.col.f32.tf32.tf32.f32 "
                 "{%0,%1,%2,%3}, {%4,%5,%6,%7}, {%8,%9}, {%0,%1,%2,%3};"
                 : "+f"(c0), "+f"(c1), "+f"(c2), "+f"(c3)
                 : "r"(a0), "r"(a1), "r"(a2), "r"(a3), "r"(b0), "r"(b1));
}
__device__ __forceinline__ void cvt_tf32(uint32_t& x) {
    asm volatile("cvt.rna.tf32.f32 %0, %0;" : "+r"(x));
}
__device__ __forceinline__ uint32_t pack_bf2(float a, float b) {
    __nv_bfloat162 h = __floats2bfloat162_rn(a, b);
    return *(uint32_t*)&h;
}
__device__ __forceinline__ float2 unpack_bf2(uint32_t u) {
    __nv_bfloat162 h = *(__nv_bfloat162*)&u;
    return make_float2(__bfloat162float(h.x), __bfloat162float(h.y));
}

// fast-math helpers (MUFU-backed approximations)
__device__ __forceinline__ float fast_tanh(float x) {
    float y; asm("tanh.approx.f32 %0, %1;" : "=f"(y) : "f"(x)); return y;
}
__device__ __forceinline__ float fast_ex2(float x) {
    float y; asm("ex2.approx.f32 %0, %1;" : "=f"(y) : "f"(x)); return y;
}
__device__ __forceinline__ float fast_lg2(float x) {
    float y; asm("lg2.approx.f32 %0, %1;" : "=f"(y) : "f"(x)); return y;
}
__device__ __forceinline__ float fast_rcp(float x) {
    float y; asm("rcp.approx.f32 %0, %1;" : "=f"(y) : "f"(x)); return y;
}
#define LOG2E_F 1.4426950408889634f
#define LN2_F   0.6931471805599453f
__device__ __forceinline__ float fast_sigmoid(float x) {
    return fast_rcp(1.f + fast_ex2(-LOG2E_F * x));
}
__device__ __forceinline__ float fast_log(float x) {
    return LN2_F * fast_lg2(x);
}

// ========== mma.sync bf16 NN GEMM for Cf/Cb (trans-B, 3-stage) — R15 proven ==========
#define CG_ST    3
#define CG_KC    64
#define CG_NCH   8
#define CG_STAGE 16384
#define CG_SMEM  (CG_ST * 2 * CG_STAGE) // 98304

__device__ __forceinline__ void cg_load_chunk(const __nv_bfloat16* Ag, const __nv_bfloat16* Bg,
                                              int m0, int c, uint32_t sA, uint32_t sB, int tid) {
    int k0 = c * CG_KC;
#pragma unroll
    for (int f = tid; f < 1024; f += 256) {
        int row = f >> 3, seg = f & 7;
        cpasync16(sA + swz128(row * 128 + seg * 16), Ag + (size_t)row * 512 + k0 + seg * 8);
    }
#pragma unroll
    for (int f = tid; f < 1024; f += 256) {
        int h = f >> 9, k = (f >> 3) & 63, seg = f & 7;
        cpasync16(sB + h * 8192 + swz128(k * 128 + seg * 16),
                  Bg + (size_t)(k0 + k) * 512 + m0 + h * 64 + seg * 8);
    }
}

__global__ __launch_bounds__(256, 2) void c_gemm_mma() {
    extern __shared__ char smem_raw[];
    uint32_t sb = smem_u32(smem_raw);
    int tid = threadIdx.x;
    int wid = tid >> 5, lane = tid & 31;
    int wm = wid >> 2, wn = wid & 3;

    int z = blockIdx.z, dir = z >> 5, bh = z & 31;
    const __nv_bfloat16* Ag = (dir ? g_A1b : g_A0b) + (size_t)bh * NM + (size_t)blockIdx.y * 128 * 512;
    const __nv_bfloat16* Bg = (dir ? g_A0b : g_A1b) + (size_t)bh * NM;
    __nv_bfloat16*       Cg = (dir ? g_Cbb : g_Cfb) + (size_t)bh * NM;
    int m0 = blockIdx.x * 128;

#pragma unroll
    for (int c = 0; c < 2; c++) {
        uint32_t st = sb + (uint32_t)c * 2 * CG_STAGE;
        cg_load_chunk(Ag, Bg, m0, c, st, st + CG_STAGE, tid);
        cp_commit();
    }

    float acc[4][4][4];
#pragma unroll
    for (int i = 0; i < 4; i++)
#pragma unroll
        for (int j = 0; j < 4; j++)
#pragma unroll
            for (int k = 0; k < 4; k++) acc[i][j][k] = 0.f;

    int rowA  = wm * 64 + (lane & 15);
    int hiA   = lane >> 4;
    int sxA   = rowA & 7;
    int krB   = lane & 15;
    int ngrpB = lane >> 4;

    for (int c = 0; c < CG_NCH; c++) {
        if (c + 2 < CG_NCH) {
            uint32_t st = sb + (uint32_t)((c + 2) % CG_ST) * 2 * CG_STAGE;
            cg_load_chunk(Ag, Bg, m0, c + 2, st, st + CG_STAGE, tid);
            cp_commit();
            cp_wait<2>();
        } else if (c + 1 < CG_NCH) {
            cp_wait<1>();
        } else {
            cp_wait<0>();
        }
        __syncthreads();
        uint32_t sA  = sb + (uint32_t)(c % CG_ST) * 2 * CG_STAGE;
        uint32_t sBm = sA + CG_STAGE;
#pragma unroll
        for (int ks = 0; ks < 4; ks++) {
            uint32_t a[4][4];
#pragma unroll
            for (int mf = 0; mf < 4; mf++) {
                uint32_t addr = sA + rowA * 128 + mf * 2048 + 16 * ((2 * ks + hiA) ^ sxA);
                ldmx4(a[mf][0], a[mf][1], a[mf][2], a[mf][3], addr);
            }
#pragma unroll
            for (int nf = 0; nf < 2; nf++) {
                int nseg = wn * 32 + nf * 16 + ngrpB * 8;
                int half = nseg >> 6, lc = nseg & 63;
                int kr = ks * 16 + krB;
                uint32_t addr = sBm + half * 8192 + swz128(kr * 128 + lc * 2);
                uint32_t b0, b1, b2, b3;
                ldmx4t(b0, b1, b2, b3, addr);
#pragma unroll
                for (int mf = 0; mf < 4; mf++) {
                    mma16816(acc[mf][2*nf  ][0], acc[mf][2*nf  ][1], acc[mf][2*nf  ][2], acc[mf][2*nf  ][3],
                             a[mf][0], a[mf][1], a[mf][2], a[mf][3], b0, b1);
                    mma16816(acc[mf][2*nf+1][0], acc[mf][2*nf+1][1], acc[mf][2*nf+1][2], acc[mf][2*nf+1][3],
                             a[mf][0], a[mf][1], a[mf][2], a[mf][3], b2, b3);
                }
            }
        }
        __syncthreads();
    }

    int r0 = blockIdx.y * 128;
#pragma unroll
    for (int mf = 0; mf < 4; mf++) {
        int r = r0 + wm * 64 + mf * 16 + (lane >> 2);
#pragma unroll
        for (int nfr = 0; nfr < 4; nfr++) {
            int col = m0 + wn * 32 + nfr * 8 + 2 * (lane & 3);
            *(uint32_t*)&Cg[(size_t)r * 512 + col]       = pack_bf2(acc[mf][nfr][0], acc[mf][nfr][1]);
            *(uint32_t*)&Cg[(size_t)(r + 8) * 512 + col] = pack_bf2(acc[mf][nfr][2], acc[mf][nfr][3]);
        }
    }
}

// ================= tf32 mma.sync NT GEMM core (128x128, 3-stage) — qkv =================
#define TF_STAGE 16384
#define TF_SMEM  (3 * 2 * TF_STAGE)      // 98304

__device__ __forceinline__ void tf_load_chunk(const float* Ag, const float* Bg,
                                              int lda, int ldb, int c,
                                              uint32_t sA, uint32_t sB, int tid) {
    int k0 = c * 32;
#pragma unroll
    for (int f = tid; f < 1024; f += 256) {
        int row = f >> 3, seg = f & 7;
        cpasync16(sA + swz128(row * 128 + seg * 16), Ag + (size_t)row * lda + k0 + seg * 4);
    }
#pragma unroll
    for (int f = tid; f < 1024; f += 256) {
        int row = f >> 3, seg = f & 7;
        cpasync16(sB + swz128(row * 128 + seg * 16), Bg + (size_t)row * ldb + k0 + seg * 4);
    }
}

__device__ __forceinline__ void tf32_core(const float* Ag, const float* Bg,
                                          int lda, int ldb, int nch,
                                          uint32_t sb, int tid, float acc[4][4][4]) {
    int lane = tid & 31, wid = tid >> 5;
    int wm = wid >> 2, wn = wid & 3;

    int npro = nch < 2 ? nch : 2;
    for (int c = 0; c < npro; c++) {
        uint32_t st = sb + (uint32_t)c * 2 * TF_STAGE;
        tf_load_chunk(Ag, Bg, lda, ldb, c, st, st + TF_STAGE, tid);
        cp_commit();
    }

    int rA_off = wm * 64 + (lane & 7) + ((lane >> 3) & 1) * 8;
    int csA    = lane >> 4;
    int rB_off = wn * 32 + (lane & 7) + (lane >> 4) * 8;
    int ksB    = (lane >> 3) & 1;

    for (int c = 0; c < nch; c++) {
        if (c + 2 < nch) {
            uint32_t st = sb + (uint32_t)((c + 2) % 3) * 2 * TF_STAGE;
            tf_load_chunk(Ag, Bg, lda, ldb, c + 2, st, st + TF_STAGE, tid);
            cp_commit();
            cp_wait<2>();
        } else if (c + 1 < nch) {
            cp_wait<1>();
        } else {
            cp_wait<0>();
        }
        __syncthreads();
        uint32_t sA = sb + (uint32_t)(c % 3) * 2 * TF_STAGE;
        uint32_t sB = sA + TF_STAGE;
#pragma unroll
        for (int ks = 0; ks < 4; ks++) {
            uint32_t a[4][4];
#pragma unroll
            for (int mf = 0; mf < 4; mf++) {
                int row = rA_off + mf * 16;
                uint32_t addr = sA + row * 128 + 16 * ((2 * ks + csA) ^ (row & 7));
                ldmx4(a[mf][0], a[mf][1], a[mf][2], a[mf][3], addr);
                cvt_tf32(a[mf][0]); cvt_tf32(a[mf][1]); cvt_tf32(a[mf][2]); cvt_tf32(a[mf][3]);
            }
            uint32_t b[2][4];
#pragma unroll
            for (int p = 0; p < 2; p++) {
                int row = rB_off + p * 16;
                uint32_t addr = sB + row * 128 + 16 * ((2 * ks + ksB) ^ (row & 7));
                ldmx4(b[p][0], b[p][1], b[p][2], b[p][3], addr);
                cvt_tf32(b[p][0]); cvt_tf32(b[p][1]); cvt_tf32(b[p][2]); cvt_tf32(b[p][3]);
            }
#pragma unroll
            for (int mf = 0; mf < 4; mf++)
#pragma unroll
                for (int p = 0; p < 2; p++) {
                    mma1688tf(acc[mf][2*p  ][0], acc[mf][2*p  ][1], acc[mf][2*p  ][2], acc[mf][2*p  ][3],
                              a[mf][0], a[mf][1], a[mf][2], a[mf][3], b[p][0], b[p][1]);
                    mma1688tf(acc[mf][2*p+1][0], acc[mf][2*p+1][1], acc[mf][2*p+1][2], acc[mf][2*p+1][3],
                              a[mf][0], a[mf][1], a[mf][2], a[mf][3], b[p][2], b[p][3]);
                }
        }
        __syncthreads();
    }
}

// ---------------- 1) QKV GEMM (tf32, 128x128 tiles) ----------------
__global__ __launch_bounds__(256, 2) void qkv_tf32(const float* __restrict__ x,
                                                   const float* __restrict__ w0,
                                                   const float* __restrict__ w1) {
    extern __shared__ char smem_raw[];
    uint32_t sb = smem_u32(smem_raw);
    int tid = threadIdx.x, lane = tid & 31, wid = tid >> 5;
    int wm = wid >> 2, wn = wid & 3;
    int set = blockIdx.z;
    const float* W = set ? w1 : w0;
    int m0 = blockIdx.y * 128, n0 = blockIdx.x * 128;

    float acc[4][4][4];
#pragma unroll
    for (int i = 0; i < 4; i++)
#pragma unroll
        for (int j = 0; j < 4; j++)
#pragma unroll
            for (int k = 0; k < 4; k++) acc[i][j][k] = 0.f;

    tf32_core(x + (size_t)m0 * 512, W + (size_t)n0 * 512, 512, 512, 16, sb, tid, acc);

    float* q = set ? g_q1 : g_q0;
    float* kk = set ? g_k1 : g_k0;
    float* v = set ? g_v1 : g_v0;
#pragma unroll
    for (int mf = 0; mf < 4; mf++) {
        int r = m0 + wm * 64 + mf * 16 + (lane >> 2);
#pragma unroll
        for (int half = 0; half < 2; half++) {
            int rr = r + half * 8;
            int b = rr >> 9, n = rr & 511;
#pragma unroll
            for (int nf = 0; nf < 4; nf++) {
                int col = n0 + wn * 32 + nf * 8 + 2 * (lane & 3);
                int t = col >> 9, rem = col & 511, h = rem >> 6, d = rem & 63;
                float* dst = (t == 0) ? q : (t == 1) ? kk : v;
                float2 val = half ? make_float2(acc[mf][nf][2], acc[mf][nf][3])
                                  : make_float2(acc[mf][nf][0], acc[mf][nf][1]);
                *(float2*)&dst[(((size_t)b*8 + h)*512 + n)*64 + d] = val;
            }
        }
    }
}

// ========== 3+4) fused S GEMM + softmax (32 rows x 512 cols per CTA) ==========
// Emits: S bf16, S^T bf16, A fp32 (pair 0 only), A bf16 — no fp32 S round-trip.
#define SS_A_OFF   0                    // 2 chunks x 32 rows x 128B = 8192
#define SS_B_OFF   8192                 // 512 rows x 128B = 65536 (single-buffered)
#define SS_RED_OFF (8192 + 65536)       // 32 x 8 floats x 2 bufs = 2048
#define SS_SMEM    (8192 + 65536 + 2048)

__global__ __launch_bounds__(256, 2) void s_sm() {
    extern __shared__ char smem_raw[];
    uint32_t sb = smem_u32(smem_raw);
    int tid = threadIdx.x, lane = tid & 31, wn = tid >> 5;   // 8 warps, all n-split
    int z = blockIdx.y, pair = z >> 5, bh = z & 31;
    int r0 = blockIdx.x * 32;

    const float* Q = (pair ? g_q1 : g_q0) + (size_t)bh * NN_ * DK + (size_t)r0 * DK;
    const float* K = (pair ? g_k1 : g_k0) + (size_t)bh * NN_ * DK;
    __nv_bfloat16* Cb  = (pair ? g_S1b  : g_S0b ) + (size_t)bh * NM;
    __nv_bfloat16* CTb = (pair ? g_S1Tb : g_S0Tb) + (size_t)bh * NM;
    __nv_bfloat16* Ab  = (pair ? g_A1b  : g_A0b ) + (size_t)bh * NM;

    uint32_t sA = sb + SS_A_OFF, sB = sb + SS_B_OFF;
    float* red  = (float*)(smem_raw + SS_RED_OFF);          // [32][8]
    float* red2 = red + 256;

    // load A both chunks + B chunk0
#pragma unroll
    for (int f = tid; f < 512; f += 256) {
        int c = f >> 8, row = (f >> 3) & 31, seg = f & 7;
        cpasync16(sA + c * 4096 + swz128(row * 128 + seg * 16),
                  Q + (size_t)row * 64 + c * 32 + seg * 4);
    }
#pragma unroll
    for (int f = tid; f < 4096; f += 256) {
        int row = f >> 3, seg = f & 7;
        cpasync16(sB + swz128(row * 128 + seg * 16), K + (size_t)row * 64 + seg * 4);
    }
    cp_commit();

    float acc[2][8][4];
#pragma unroll
    for (int i = 0; i < 2; i++)
#pragma unroll
        for (int j = 0; j < 8; j++)
#pragma unroll
            for (int k = 0; k < 4; k++) acc[i][j][k] = 0.f;

    int rA_off = (lane & 7) + ((lane >> 3) & 1) * 8;   // + mf*16
    int csA    = lane >> 4;
    int rB_grp = (lane & 7) + (lane >> 4) * 8;          // + wn*64 + p*16
    int ksB    = (lane >> 3) & 1;

    cp_wait<0>();
    __syncthreads();

#pragma unroll
    for (int c = 0; c < 2; c++) {
        if (c == 1) {
            __syncthreads();      // all warps done with B chunk0
#pragma unroll
            for (int f = tid; f < 4096; f += 256) {
                int row = f >> 3, seg = f & 7;
                cpasync16(sB + swz128(row * 128 + seg * 16), K + (size_t)row * 64 + 32 + seg * 4);
            }
            cp_commit();
            cp_wait<0>();
            __syncthreads();
        }
#pragma unroll
        for (int ks = 0; ks < 4; ks++) {
            uint32_t a[2][4];
#pragma unroll
            for (int mf = 0; mf < 2; mf++) {
                int row = rA_off + mf * 16;
                uint32_t addr = sA + c * 4096 + row * 128 + 16 * ((2 * ks + csA) ^ (row & 7));
                ldmx4(a[mf][0], a[mf][1], a[mf][2], a[mf][3], addr);
                cvt_tf32(a[mf][0]); cvt_tf32(a[mf][1]); cvt_tf32(a[mf][2]); cvt_tf32(a[mf][3]);
            }
#pragma unroll
            for (int p = 0; p < 4; p++) {
                int row = wn * 64 + p * 16 + rB_grp;
                uint32_t addr = sB + row * 128 + 16 * ((2 * ks + ksB) ^ (row & 7));
                uint32_t b0, b1, b2, b3;
                ldmx4(b0, b1, b2, b3, addr);
                cvt_tf32(b0); cvt_tf32(b1); cvt_tf32(b2); cvt_tf32(b3);
#pragma unroll
                for (int mf = 0; mf < 2; mf++) {
                    mma1688tf(acc[mf][2*p  ][0], acc[mf][2*p  ][1], acc[mf][2*p  ][2], acc[mf][2*p  ][3],
                              a[mf][0], a[mf][1], a[mf][2], a[mf][3], b0, b1);
                    mma1688tf(acc[mf][2*p+1][0], acc[mf][2*p+1][1], acc[mf][2*p+1][2], acc[mf][2*p+1][3],
                              a[mf][0], a[mf][1], a[mf][2], a[mf][3], b2, b3);
                }
            }
        }
    }
    __syncthreads();

    // scale logits
#pragma unroll
    for (int i = 0; i < 2; i++)
#pragma unroll
        for (int j = 0; j < 8; j++)
#pragma unroll
            for (int k = 0; k < 4; k++) acc[i][j][k] *= 0.125f;

    int g = lane >> 2;  // row group 0..7; rows owned: mf*16 + half*8 + g

    // ---- row max ----
#pragma unroll
    for (int mf = 0; mf < 2; mf++)
#pragma unroll
        for (int half = 0; half < 2; half++) {
            float m = -1e30f;
#pragma unroll
            for (int nf = 0; nf < 8; nf++)
                m = fmaxf(m, fmaxf(acc[mf][nf][half*2], acc[mf][nf][half*2+1]));
            m = fmaxf(m, __shfl_xor_sync(0xffffffffu, m, 1));
            m = fmaxf(m, __shfl_xor_sync(0xffffffffu, m, 2));
            if ((lane & 3) == 0) red[(mf*16 + half*8 + g) * 8 + wn] = m;
        }
    __syncthreads();
    float mx[2][2];
#pragma unroll
    for (int mf = 0; mf < 2; mf++)
#pragma unroll
        for (int half = 0; half < 2; half++) {
            int row = mf*16 + half*8 + g;
            float m = red[row*8+0];
#pragma unroll
            for (int w = 1; w < 8; w++) m = fmaxf(m, red[row*8+w]);
            mx[mf][half] = m;
        }

    // ---- stores of S (bf16) + S^T staging, while acc still holds s ----
#pragma unroll
    for (int mf = 0; mf < 2; mf++)
#pragma unroll
        for (int half = 0; half < 2; half++) {
            int rl = mf*16 + half*8 + g;
            int rg = r0 + rl;
#pragma unroll
            for (int nf = 0; nf < 8; nf++) {
                int col = wn*64 + nf*8 + 2*(lane & 3);
                *(uint32_t*)&Cb[(size_t)rg * 512 + col] =
                    pack_bf2(acc[mf][nf][half*2], acc[mf][nf][half*2+1]);
            }
        }
    __syncthreads();   // B smem free for staging
    {
        __nv_bfloat16* tile = (__nv_bfloat16*)(smem_raw + SS_B_OFF);  // [512][36]
#pragma unroll
        for (int mf = 0; mf < 2; mf++)
#pragma unroll
            for (int half = 0; half < 2; half++) {
                int rl = mf*16 + half*8 + g;
#pragma unroll
                for (int nf = 0; nf < 8; nf++) {
                    int col = wn*64 + nf*8 + 2*(lane & 3);
                    tile[col * 36 + rl]       = __float2bfloat16(acc[mf][nf][half*2]);
                    tile[(col + 1) * 36 + rl] = __float2bfloat16(acc[mf][nf][half*2+1]);
                }
            }
        __syncthreads();
#pragma unroll
        for (int f = tid; f < 4096; f += 256) {
            int c = f >> 3, seg = f & 7;
            uint2 val = *(uint2*)&tile[c * 36 + seg * 4];
            *(uint2*)&CTb[(size_t)c * 512 + r0 + seg * 4] = val;
        }
    }

    // ---- exp (overwrite acc) + row sum ----
#pragma unroll
    for (int mf = 0; mf < 2; mf++)
#pragma unroll
        for (int half = 0; half < 2; half++) {
            float s = 0.f;
#pragma unroll
            for (int nf = 0; nf < 8; nf++) {
                float p0 = expf(acc[mf][nf][half*2]   - mx[mf][half]);
                float p1 = expf(acc[mf][nf][half*2+1] - mx[mf][half]);
                acc[mf][nf][half*2]   = p0;
                acc[mf][nf][half*2+1] = p1;
                s += p0 + p1;
            }
            s += __shfl_xor_sync(0xffffffffu, s, 1);
            s += __shfl_xor_sync(0xffffffffu, s, 2);
            if ((lane & 3) == 0) red2[(mf*16 + half*8 + g) * 8 + wn] = s;
        }
    __syncthreads();

    float* A0g = g_A0 + (size_t)bh * NM;
#pragma unroll
    for (int mf = 0; mf < 2; mf++)
#pragma unroll
        for (int half = 0; half < 2; half++) {
            int rl = mf*16 + half*8 + g;
            int rg = r0 + rl;
            float sum = 0.f;
#pragma unroll
            for (int w = 0; w < 8; w++) sum += red2[rl*8 + w];
            float inv = 1.f / sum;
#pragma unroll
            for (int nf = 0; nf < 8; nf++) {
                int col = wn*64 + nf*8 + 2*(lane & 3);
                float a0 = acc[mf][nf][half*2]   * inv;
                float a1 = acc[mf][nf][half*2+1] * inv;
                if (pair == 0)
                    *(float2*)&A0g[(size_t)rg * 512 + col] = make_float2(a0, a1);
                *(uint32_t*)&Ab[(size_t)rg * 512 + col] = pack_bf2(a0, a1);
            }
        }
}

// ================= 64x128-tile tf32 core (proj) =================
#define PJ_ST_A  8192
#define PJ_ST_B  16384
#define PJ_STAGE (PJ_ST_A + PJ_ST_B)     // 24576
#define PJ_SMEM  (3 * PJ_STAGE)          // 73728

__device__ __forceinline__ void pj_load_chunk(const float* Ag, const float* Bg, int c,
                                              uint32_t sA, uint32_t sB, int tid) {
    int k0 = c * 32;
#pragma unroll
    for (int f = tid; f < 512; f += 256) {
        int row = f >> 3, seg = f & 7;
        cpasync16(sA + swz128(row * 128 + seg * 16), Ag + (size_t)row * 512 + k0 + seg * 4);
    }
#pragma unroll
    for (int f = tid; f < 1024; f += 256) {
        int row = f >> 3, seg = f & 7;
        cpasync16(sB + swz128(row * 128 + seg * 16), Bg + (size_t)row * 512 + k0 + seg * 4);
    }
}

__device__ __forceinline__ void pj_core(const float* Ag, const float* Bg,
                                        uint32_t sb, int tid, float acc[2][4][4]) {
    int lane = tid & 31, wid = tid >> 5;
    int wm = wid >> 2, wn = wid & 3;

#pragma unroll
    for (int c = 0; c < 2; c++) {
        uint32_t st = sb + (uint32_t)c * PJ_STAGE;
        pj_load_chunk(Ag, Bg, c, st, st + PJ_ST_A, tid);
        cp_commit();
    }

    int rA_off = wm * 32 + (lane & 7) + ((lane >> 3) & 1) * 8;
    int csA    = lane >> 4;
    int rB_off = wn * 32 + (lane & 7) + (lane >> 4) * 8;
    int ksB    = (lane >> 3) & 1;

    for (int c = 0; c < 16; c++) {
        if (c + 2 < 16) {
            uint32_t st = sb + (uint32_t)((c + 2) % 3) * PJ_STAGE;
            pj_load_chunk(Ag, Bg, c + 2, st, st + PJ_ST_A, tid);
            cp_commit();
            cp_wait<2>();
        } else if (c + 1 < 16) {
            cp_wait<1>();
        } else {
            cp_wait<0>();
        }
        __syncthreads();
        uint32_t sA = sb + (uint32_t)(c % 3) * PJ_STAGE;
        uint32_t sB = sA + PJ_ST_A;
#pragma unroll
        for (int ks = 0; ks < 4; ks++) {
            uint32_t a[2][4];
#pragma unroll
            for (int mf = 0; mf < 2; mf++) {
                int row = rA_off + mf * 16;
                uint32_t addr = sA + row * 128 + 16 * ((2 * ks + csA) ^ (row & 7));
                ldmx4(a[mf][0], a[mf][1], a[mf][2], a[mf][3], addr);
                cvt_tf32(a[mf][0]); cvt_tf32(a[mf][1]); cvt_tf32(a[mf][2]); cvt_tf32(a[mf][3]);
            }
            uint32_t b[2][4];
#pragma unroll
            for (int p = 0; p < 2; p++) {
                int row = rB_off + p * 16;
                uint32_t addr = sB + row * 128 + 16 * ((2 * ks + ksB) ^ (row & 7));
                ldmx4(b[p][0], b[p][1], b[p][2], b[p][3], addr);
                cvt_tf32(b[p][0]); cvt_tf32(b[p][1]); cvt_tf32(b[p][2]); cvt_tf32(b[p][3]);
            }
#pragma unroll
            for (int mf = 0; mf < 2; mf++)
#pragma unroll
                for (int p = 0; p < 2; p++) {
                    mma1688tf(acc[mf][2*p  ][0], acc[mf][2*p  ][1], acc[mf][2*p  ][2], acc[mf][2*p  ][3],
                              a[mf][0], a[mf][1], a[mf][2], a[mf][3], b[p][0], b[p][1]);
                    mma1688tf(acc[mf][2*p+1][0], acc[mf][2*p+1][1], acc[mf][2*p+1][2], acc[mf][2*p+1][3],
                              a[mf][0], a[mf][1], a[mf][2], a[mf][3], b[p][2], b[p][3]);
                }
        }
        __syncthreads();
    }
}

// ---------------- 9) final projection (64x128 tiles) ----------------
__global__ __launch_bounds__(256, 2) void proj_tf32(const float* __restrict__ wp,
                                                    float* __restrict__ out) {
    extern __shared__ char smem_raw[];
    uint32_t sb = smem_u32(smem_raw);
    int tid = threadIdx.x, lane = tid & 31, wid = tid >> 5;
    int wm = wid >> 2, wn = wid & 3;
    int m0 = blockIdx.y * 64, n0 = blockIdx.x * 128;

    float acc[2][4][4];
#pragma unroll
    for (int i = 0; i < 2; i++)
#pragma unroll
        for (int j = 0; j < 4; j++)
#pragma unroll
            for (int k = 0; k < 4; k++) acc[i][j][k] = 0.f;

    pj_core(g_attn + (size_t)m0 * 512, wp + (size_t)n0 * 512, sb, tid, acc);

#pragma unroll
    for (int mf = 0; mf < 2; mf++) {
        int r = m0 + wm * 32 + mf * 16 + (lane >> 2);
#pragma unroll
        for (int nf = 0; nf < 4; nf++) {
            int col = n0 + wn * 32 + nf * 8 + 2 * (lane & 3);
            *(float2*)&out[(size_t)r * 512 + col]       = make_float2(acc[mf][nf][0], acc[mf][nf][1]);
            *(float2*)&out[(size_t)(r + 8) * 512 + col] = make_float2(acc[mf][nf][2], acc[mf][nf][3]);
        }
    }
}

// ================= 8) mv — 64x64 tiles (256 CTAs) =================
#define MV_ST_A  8192
#define MV_ST_B  8192
#define MV_STAGE (MV_ST_A + MV_ST_B)     // 16384
#define MV_SMEM  (3 * MV_STAGE)          // 49152

__device__ __forceinline__ void mv_load_chunk(const float* Ag, const float* Bg, int c,
                                              uint32_t sA, uint32_t sB, int tid) {
    int k0 = c * 32;
#pragma unroll
    for (int f = tid; f < 512; f += 256) {
        int row = f >> 3, seg = f & 7;
        cpasync16(sA + swz128(row * 128 + seg * 16), Ag + (size_t)row * 512 + k0 + seg * 4);
    }
#pragma unroll
    for (int f = tid; f < 512; f += 256) {
        int row = f >> 3, seg = f & 7;
        cpasync16(sB + swz128(row * 128 + seg * 16), Bg + (size_t)row * 512 + k0 + seg * 4);
    }
}

__global__ __launch_bounds__(256, 2) void mv_tf32() {
    extern __shared__ char smem_raw[];
    uint32_t sb = smem_u32(smem_raw);
    int tid = threadIdx.x, lane = tid & 31, wid = tid >> 5;
    int wm = wid >> 2, wn = wid & 3;
    int z = blockIdx.z;
    int m0 = blockIdx.y * 64;

    const float* Ag = g_M  + (size_t)z * NM + (size_t)m0 * 512;
    const float* Bg = g_vT + (size_t)z * DK * 512;

    float acc[2][2][4];
#pragma unroll
    for (int i = 0; i < 2; i++)
#pragma unroll
        for (int j = 0; j < 2; j++)
#pragma unroll
            for (int k = 0; k < 4; k++) acc[i][j][k] = 0.f;

#pragma unroll
    for (int c = 0; c < 2; c++) {
        uint32_t st = sb + (uint32_t)c * MV_STAGE;
        mv_load_chunk(Ag, Bg, c, st, st + MV_ST_A, tid);
        cp_commit();
    }

    int rA_off = wm * 32 + (lane & 7) + ((lane >> 3) & 1) * 8;
    int csA    = lane >> 4;
    int rB_off = wn * 16 + (lane & 7) + (lane >> 4) * 8;
    int ksB    = (lane >> 3) & 1;

    for (int c = 0; c < 16; c++) {
        if (c + 2 < 16) {
            uint32_t st = sb + (uint32_t)((c + 2) % 3) * MV_STAGE;
            mv_load_chunk(Ag, Bg, c + 2, st, st + MV_ST_A, tid);
            cp_commit();
            cp_wait<2>();
        } else if (c + 1 < 16) {
            cp_wait<1>();
        } else {
            cp_wait<0>();
        }
        __syncthreads();
        uint32_t sA = sb + (uint32_t)(c % 3) * MV_STAGE;
        uint32_t sB = sA + MV_ST_A;
#pragma unroll
        for (int ks = 0; ks < 4; ks++) {
            uint32_t a[2][4];
#pragma unroll
            for (int mf = 0; mf < 2; mf++) {
                int row = rA_off + mf * 16;
                uint32_t addr = sA + row * 128 + 16 * ((2 * ks + csA) ^ (row & 7));
                ldmx4(a[mf][0], a[mf][1], a[mf][2], a[mf][3], addr);
                cvt_tf32(a[mf][0]); cvt_tf32(a[mf][1]); cvt_tf32(a[mf][2]); cvt_tf32(a[mf][3]);
            }
            uint32_t b0, b1, b2, b3;
            {
                int row = rB_off;
                uint32_t addr = sB + row * 128 + 16 * ((2 * ks + ksB) ^ (row & 7));
                ldmx4(b0, b1, b2, b3, addr);
                cvt_tf32(b0); cvt_tf32(b1); cvt_tf32(b2); cvt_tf32(b3);
            }
#pragma unroll
            for (int mf = 0; mf < 2; mf++) {
                mma1688tf(acc[mf][0][0], acc[mf][0][1], acc[mf][0][2], acc[mf][0][3],
                          a[mf][0], a[mf][1], a[mf][2], a[mf][3], b0, b1);
                mma1688tf(acc[mf][1][0], acc[mf][1][1], acc[mf][1][2], acc[mf][1][3],
                          a[mf][0], a[mf][1], a[mf][2], a[mf][3], b2, b3);
            }
        }
        __syncthreads();
    }

    int b = z >> 3, h = z & 7;
#pragma unroll
    for (int mf = 0; mf < 2; mf++) {
        int n = m0 + wm * 32 + mf * 16 + (lane >> 2);
        float sc0 = 1.f / (g_rowsum[z * 512 + n] + EPSF);
        float sc1 = 1.f / (g_rowsum[z * 512 + n + 8] + EPSF);
#pragma unroll
        for (int nf = 0; nf < 2; nf++) {
            int d = wn * 16 + nf * 8 + 2 * (lane & 3);
            *(float2*)&g_attn[((size_t)b * 512 + n) * 512 + h * 64 + d] =
                make_float2(acc[mf][nf][0] * sc0, acc[mf][nf][1] * sc0);
            *(float2*)&g_attn[((size_t)b * 512 + n + 8) * 512 + h * 64 + d] =
                make_float2(acc[mf][nf][2] * sc1, acc[mf][nf][3] * sc1);
        }
    }
}

// ---------------- 2) v mix + transpose: vT[bh][d][n], d = 0..63 ----------------
__global__ void vmix_k(const float* __restrict__ cl) {
    __shared__ float t[32][33];
    float a = fast_sigmoid(cl[0]);
    int bh = blockIdx.z;
    int d0 = blockIdx.x * 32, n0 = blockIdx.y * 32;
    const float* v0 = g_v0 + (size_t)bh * NN_ * DK;
    const float* v1 = g_v1 + (size_t)bh * NN_ * DK;
    float* vt = g_vT + (size_t)bh * DK * 512;
    int tx = threadIdx.x, ty = threadIdx.y;
#pragma unroll
    for (int i = 0; i < 32; i += 8) {
        size_t idx = (size_t)(n0 + ty + i) * 64 + d0 + tx;
        t[ty + i][tx] = (1.f - a) * v0[idx] + a * v1[idx];
    }
    __syncthreads();
#pragma unroll
    for (int i = 0; i < 32; i += 8)
        vt[(size_t)(d0 + ty + i) * 512 + n0 + tx] = t[tx][ty + i];
}

// ---------------- 7) gate + combine (vectorized: 2 elems/thread, 1 pass) ----------
__global__ void gate_k(const float* __restrict__ c1w, const float* __restrict__ c1b,
                       const float* __restrict__ c2w, const float* __restrict__ c2b) {
    int row = blockIdx.x;
    size_t base = (size_t)row * 512;
    __shared__ float sw1[96], sb1[16], sw2[64], sb2[4];
    int tid = threadIdx.x;
    if (tid < 96)       sw1[tid]       = c1w[tid];
    else if (tid < 112) sb1[tid - 96]  = c1b[tid - 96];
    else if (tid < 176) sw2[tid - 112] = c2w[tid - 112];
    else if (tid < 180) sb2[tid - 176] = c2b[tid - 176];
    __syncthreads();

    int m = tid * 2;
    float2 f0v = unpack_bf2(*(const uint32_t*)&g_S0b [base + m]);
    float2 f1v = unpack_bf2(*(const uint32_t*)&g_S1b [base + m]);
    float2 f2v = unpack_bf2(*(const uint32_t*)&g_S0Tb[base + m]);
    float2 f3v = unpack_bf2(*(const uint32_t*)&g_S1Tb[base + m]);
    float2 cfv = unpack_bf2(*(const uint32_t*)&g_Cfb [base + m]);
    float2 cbv = unpack_bf2(*(const uint32_t*)&g_Cbb [base + m]);
    float2 a0v = *(const float2*)&g_A0[base + m];
    float2 a1v = unpack_bf2(*(const uint32_t*)&g_A1b[base + m]);

    float f0a[2] = { f0v.x, f0v.y }, f1a[2] = { f1v.x, f1v.y };
    float f2a[2] = { f2v.x, f2v.y }, f3a[2] = { f3v.x, f3v.y };
    float cfa[2] = { cfv.x, cfv.y }, cba[2] = { cbv.x, cbv.y };
    float a0a[2] = { a0v.x, a0v.y }, a1a[2] = { a1v.x, a1v.y };
    float mv[2];
    float lsum = 0.f;
#pragma unroll
    for (int e = 0; e < 2; e++) {
        float f4 = fast_log(cfa[e] + EPSF);
        float f5 = fast_log(cba[e] + EPSF);
        float a2[4] = { sb2[0], sb2[1], sb2[2], sb2[3] };
#pragma unroll
        for (int o = 0; o < 16; o++) {
            float h = sb1[o] + sw1[o*6+0]*f0a[e] + sw1[o*6+1]*f1a[e] + sw1[o*6+2]*f2a[e]
                             + sw1[o*6+3]*f3a[e] + sw1[o*6+4]*f4     + sw1[o*6+5]*f5;
            float u = 0.7978845608028654f * (h + 0.044715f * h * h * h);
            float g = 0.5f * h * (1.f + fast_tanh(u));
            a2[0] += sw2[ 0 + o] * g;
            a2[1] += sw2[16 + o] * g;
            a2[2] += sw2[32 + o] * g;
            a2[3] += sw2[48 + o] * g;
        }
        float G0 = fast_sigmoid(a2[0]);
        float G1 = fast_sigmoid(a2[1]);
        float G2 = fast_sigmoid(a2[2]);
        float G3 = fast_sigmoid(a2[3]);
        float aand = a0a[e] * a1a[e];
        float aor  = a0a[e] + a1a[e] - aand;
        float anot = a0a[e] * (1.f - 0.5f * a1a[e]);
        mv[e] = a0a[e] + G0*aand + G1*aor + G2*anot + G3*cfa[e];
        lsum += mv[e];
    }
    *(float2*)&g_M[base + m] = make_float2(mv[0], mv[1]);

    __shared__ float red[256];
    red[tid] = lsum;
    __syncthreads();
    for (int s = 128; s > 0; s >>= 1) { if (tid < s) red[tid] += red[tid+s]; __syncthreads(); }
    if (tid == 0) g_rowsum[row] = red[0];
}

// ---------------- launch ----------------
extern "C" void kernel_launch(void* const* d_in, const int* in_sizes, int n_in,
                              void* d_out, int out_size) {
    const float* x    = (const float*)d_in[0];
    const float* w0   = (const float*)d_in[1];
    const float* w1   = (const float*)d_in[2];
    const float* c1w  = (const float*)d_in[3];
    const float* c1b  = (const float*)d_in[4];
    const float* c2w  = (const float*)d_in[5];
    const float* c2b  = (const float*)d_in[6];
    const float* wp   = (const float*)d_in[7];
    const float* cl   = (const float*)d_in[8];
    float* out = (float*)d_out;

    cudaFuncSetAttribute(c_gemm_mma, cudaFuncAttributeMaxDynamicSharedMemorySize, CG_SMEM);
    cudaFuncSetAttribute(qkv_tf32,   cudaFuncAttributeMaxDynamicSharedMemorySize, TF_SMEM);
    cudaFuncSetAttribute(s_sm,       cudaFuncAttributeMaxDynamicSharedMemorySize, SS_SMEM);
    cudaFuncSetAttribute(mv_tf32,    cudaFuncAttributeMaxDynamicSharedMemorySize, MV_SMEM);
    cudaFuncSetAttribute(proj_tf32,  cudaFuncAttributeMaxDynamicSharedMemorySize, PJ_SMEM);

    qkv_tf32   <<<dim3(12, 16, 2), 256, TF_SMEM>>>(x, w0, w1);
    vmix_k     <<<dim3(2, 16, 32), dim3(32, 8)>>>(cl);
    s_sm       <<<dim3(16, 64), 256, SS_SMEM>>>();
    c_gemm_mma <<<dim3(4, 4, 64), 256, CG_SMEM>>>();
    gate_k     <<<16384, 256>>>(c1w, c1b, c2w, c2b);
    mv_tf32    <<<dim3(1, 8, 32), 256, MV_SMEM>>>();
    proj_tf32  <<<dim3(4, 32, 1), 256, PJ_SMEM>>>(wp, out);
}